// round 1
// baseline (speedup 1.0000x reference)
#include <cuda_runtime.h>
#include <cstdint>

#define EPSQ 1e-8f

static const int BATCH = 16;
static const int NI = 15488;   // capsules = 256*22*22/8
static const int NJ = 10;
static const int ND = 16;

// ---------------- scratch (device globals; no allocation allowed) ----------------
__device__ float g_c1[(size_t)16 * 256 * 56 * 56];     // 51.4 MB
__device__ float g_c2[(size_t)16 * 256 * 52 * 52];     // 44.3 MB
__device__ float g_p [(size_t)16 * 256 * 22 * 22];     // 7.9 MB
__device__ float g_u [(size_t)16 * 15488 * 8];         // 7.9 MB
__device__ float g_uhat[(size_t)16 * 15488 * 10 * 16]; // 158.6 MB
__device__ float g_w2t[256 * 256 * 25];                // conv2 weights transposed
__device__ float g_wpt[(size_t)256 * 256 * 81];        // pc weights transposed
__device__ float g_s[16 * 160];
__device__ float g_V[16 * 160];
__device__ float g_masked[16 * 160];
__device__ float g_d1[16 * 512];
__device__ float g_d2[16 * 1024];

// ---------------- weight transform: w[oc][ic][khw] -> wt[ocg][ic][khw][oc%64] ----------------
__global__ void transform_w_kernel(const float* __restrict__ w, float* __restrict__ wt,
                                   int IC, int KHW) {
    int idx = blockIdx.x * 256 + threadIdx.x;
    int total = 256 * IC * KHW;
    if (idx >= total) return;
    int o   = idx & 63;
    int r   = idx >> 6;
    int khw = r % KHW; r /= KHW;
    int ic  = r % IC;
    int ocg = r / IC;
    wt[idx] = w[((size_t)(ocg * 64 + o) * IC + ic) * KHW + khw];
}

// ---------------- conv1: 1->256, 9x9, s1, 64->56 ----------------
__global__ __launch_bounds__(196)
void conv1_kernel(const float* __restrict__ x, const float* __restrict__ w,
                  const float* __restrict__ bias, float* __restrict__ out) {
    __shared__ float s_in[22 * 22];
    __shared__ float s_w[4 * 81];
    int tid = threadIdx.x;
    int tileY = blockIdx.x >> 2, tileX = blockIdx.x & 3;
    int b = blockIdx.z;
    int ocg = blockIdx.y;  // 8 groups of 32 oc

    for (int idx = tid; idx < 484; idx += 196) {
        int r = idx / 22, cc = idx % 22;
        s_in[idx] = x[((size_t)b * 64 + tileY * 14 + r) * 64 + tileX * 14 + cc];
    }
    int sy = tid / 14, sx = tid % 14;

    for (int oi = 0; oi < 32; oi += 4) {
        __syncthreads();
        for (int idx = tid; idx < 4 * 81; idx += 196) {
            int o = idx / 81, k = idx % 81;
            s_w[idx] = w[(size_t)(ocg * 32 + oi + o) * 81 + k];
        }
        __syncthreads();
        float a0 = 0.f, a1 = 0.f, a2 = 0.f, a3 = 0.f;
        for (int ky = 0; ky < 9; ky++) {
            #pragma unroll
            for (int kx = 0; kx < 9; kx++) {
                float v = s_in[(sy + ky) * 22 + sx + kx];
                int k = ky * 9 + kx;
                a0 += v * s_w[k];
                a1 += v * s_w[81 + k];
                a2 += v * s_w[162 + k];
                a3 += v * s_w[243 + k];
            }
        }
        int oc = ocg * 32 + oi;
        size_t ob = (((size_t)b * 256 + oc) * 56 + tileY * 14 + sy) * 56 + tileX * 14 + sx;
        out[ob]               = fmaxf(a0 + bias[oc],     0.f);
        out[ob + 56 * 56]     = fmaxf(a1 + bias[oc + 1], 0.f);
        out[ob + 2 * 56 * 56] = fmaxf(a2 + bias[oc + 2], 0.f);
        out[ob + 3 * 56 * 56] = fmaxf(a3 + bias[oc + 3], 0.f);
    }
}

// ---------------- generic tiled direct conv (GEMM-style) ----------------
// block tile: 64 oc x 8x8 spatial; thread: 4 oc x 4 spatial register tile
template<int IC, int KH, int KW, int IH, int IW, int OH, int OW, int STRIDE, int ICC, bool RELU>
__global__ __launch_bounds__(256)
void conv_tile_kernel(const float* __restrict__ in, const float* __restrict__ wt,
                      const float* __restrict__ bias, float* __restrict__ out) {
    constexpr int TIN = 7 * STRIDE + KH;
    constexpr int KHW = KH * KW;
    constexpr int TILESX = (OW + 7) / 8;
    __shared__ float s_in[ICC * TIN * TIN];
    __shared__ float s_w[ICC * KHW * 64];

    const int tid = threadIdx.x;
    const int tileY = blockIdx.x / TILESX;
    const int tileX = blockIdx.x % TILESX;
    const int ocg = blockIdx.y;
    const int b = blockIdx.z;

    const int tx  = tid & 15;          // oc quad: oc = ocg*64 + tx*4 + o
    const int tyq = tid >> 4;          // spatial quad
    const int sy  = tyq >> 1;          // 0..7
    const int sx0 = (tyq & 1) * 4;     // 0 or 4

    float acc[4][4];
    #pragma unroll
    for (int o = 0; o < 4; o++)
        #pragma unroll
        for (int q = 0; q < 4; q++) acc[o][q] = 0.f;

    const int iy0 = tileY * 8 * STRIDE;
    const int ix0 = tileX * 8 * STRIDE;

    for (int ic0 = 0; ic0 < IC; ic0 += ICC) {
        for (int idx = tid; idx < ICC * TIN * TIN; idx += 256) {
            int c   = idx / (TIN * TIN);
            int rem = idx - c * (TIN * TIN);
            int r   = rem / TIN;
            int col = rem - r * TIN;
            int iy = iy0 + r, ix = ix0 + col;
            float v = 0.f;
            if (iy < IH && ix < IW)
                v = in[(((size_t)b * IC + (ic0 + c)) * IH + iy) * IW + ix];
            s_in[idx] = v;
        }
        const float* wg = wt + (size_t)(ocg * IC + ic0) * KHW * 64;
        for (int idx = tid; idx < ICC * KHW * 64; idx += 256)
            s_w[idx] = wg[idx];
        __syncthreads();

        #pragma unroll
        for (int c = 0; c < ICC; c++) {
            for (int ky = 0; ky < KH; ky++) {
                #pragma unroll
                for (int kx = 0; kx < KW; kx++) {
                    const float* ip = &s_in[c * TIN * TIN + (sy * STRIDE + ky) * TIN + kx];
                    float iv[4];
                    #pragma unroll
                    for (int q = 0; q < 4; q++) iv[q] = ip[(sx0 + q) * STRIDE];
                    const float* wp = &s_w[(c * KHW + ky * KW + kx) * 64 + tx * 4];
                    float wv0 = wp[0], wv1 = wp[1], wv2 = wp[2], wv3 = wp[3];
                    #pragma unroll
                    for (int q = 0; q < 4; q++) {
                        acc[0][q] += wv0 * iv[q];
                        acc[1][q] += wv1 * iv[q];
                        acc[2][q] += wv2 * iv[q];
                        acc[3][q] += wv3 * iv[q];
                    }
                }
            }
        }
        __syncthreads();
    }

    #pragma unroll
    for (int o = 0; o < 4; o++) {
        int oc = ocg * 64 + tx * 4 + o;
        float bv = bias[oc];
        int oy = tileY * 8 + sy;
        if (oy >= OH) continue;
        #pragma unroll
        for (int q = 0; q < 4; q++) {
            int ox = tileX * 8 + sx0 + q;
            if (ox >= OW) continue;
            float v = acc[o][q] + bv;
            if (RELU) v = fmaxf(v, 0.f);
            out[(((size_t)b * 256 + oc) * OH + oy) * OW + ox] = v;
        }
    }
}

// ---------------- squash primary caps: p -> u ----------------
__global__ void squash_u_kernel() {
    int cap = blockIdx.x * 256 + threadIdx.x;
    if (cap >= BATCH * NI) return;
    const float4* pp = (const float4*)(g_p + (size_t)cap * 8);
    float4 a = pp[0], c = pp[1];
    float s2 = a.x * a.x + a.y * a.y + a.z * a.z + a.w * a.w
             + c.x * c.x + c.y * c.y + c.z * c.z + c.w * c.w;
    float f = s2 / (1.f + s2) * rsqrtf(s2 + EPSQ);
    a.x *= f; a.y *= f; a.z *= f; a.w *= f;
    c.x *= f; c.y *= f; c.z *= f; c.w *= f;
    float4* uo = (float4*)(g_u + (size_t)cap * 8);
    uo[0] = a; uo[1] = c;
}

// ---------------- u_hat[b,i,j,d] = sum_k W[j,i,d,k]*u[b,i,k] ----------------
__global__ __launch_bounds__(256)
void uhat_kernel(const float* __restrict__ W) {
    int gid = blockIdx.x * 256 + threadIdx.x;
    int d = gid & 15;
    int j = (gid >> 4) % 10;
    int i = gid / 160;
    if (i >= NI) return;
    const float4* Wp = (const float4*)(W + (((size_t)j * NI + i) * 16 + d) * 8);
    float4 w0 = Wp[0], w1 = Wp[1];
    for (int b = 0; b < BATCH; b++) {
        const float4* up = (const float4*)(g_u + ((size_t)b * NI + i) * 8);
        float4 u0 = up[0], u1 = up[1];
        float acc = w0.x * u0.x + w0.y * u0.y + w0.z * u0.z + w0.w * u0.w
                  + w1.x * u1.x + w1.y * u1.y + w1.z * u1.z + w1.w * u1.w;
        g_uhat[(((size_t)b * NI + i) * 10 + j) * 16 + d] = acc;
    }
}

// ---------------- routing: s[b,j,d] = sum_i softmax_j(u_hat*Vcum) * u_hat ----------------
__global__ __launch_bounds__(256)
void routing_s_kernel() {
    __shared__ float Vsh[160];
    __shared__ float ssh[160];
    int tid = threadIdx.x;
    int b = blockIdx.y;
    if (tid < 160) { Vsh[tid] = g_V[b * 160 + tid]; ssh[tid] = 0.f; }
    __syncthreads();
    int d = tid & 15, il = tid >> 4;
    float accj[10];
    #pragma unroll
    for (int j = 0; j < 10; j++) accj[j] = 0.f;

    const int per = NI / 32;  // gridDim.x == 32, 15488/32 = 484
    int i0 = blockIdx.x * per;
    for (int i = i0 + il; i < i0 + per; i += 16) {
        const float* uh = g_uhat + (((size_t)b * NI + i) * 10) * 16 + d;
        float uv[10], e[10];
        float m = -1e30f;
        #pragma unroll
        for (int j = 0; j < 10; j++) {
            uv[j] = uh[j * 16];
            float l = uv[j] * Vsh[j * 16 + d];
            e[j] = l;
            m = fmaxf(m, l);
        }
        float se = 0.f;
        #pragma unroll
        for (int j = 0; j < 10; j++) { e[j] = __expf(e[j] - m); se += e[j]; }
        float inv = 1.f / se;
        #pragma unroll
        for (int j = 0; j < 10; j++) accj[j] += e[j] * inv * uv[j];
    }
    #pragma unroll
    for (int j = 0; j < 10; j++) atomicAdd(&ssh[j * 16 + d], accj[j]);
    __syncthreads();
    if (tid < 160) atomicAdd(&g_s[b * 160 + tid], ssh[tid]);
}

// ---------------- v = squash(s); Vcum += v; final: out_caps + argmax mask ----------------
__global__ void v_update_kernel(int last, float* __restrict__ dout) {
    __shared__ float s2sh[10];
    __shared__ float nrm[10];
    __shared__ int amax;
    int b = blockIdx.x, tid = threadIdx.x;  // 160 threads
    int j = tid >> 4, d = tid & 15;
    if (tid < 10) s2sh[tid] = 0.f;
    __syncthreads();
    float sv = g_s[b * 160 + tid];
    atomicAdd(&s2sh[j], sv * sv);
    __syncthreads();
    float s2 = s2sh[j];
    float v = s2 / (1.f + s2) * sv * rsqrtf(s2 + EPSQ);
    if (!last) {
        g_V[b * 160 + tid] += v;
    } else {
        if (d == 0) nrm[j] = s2 / (1.f + s2) * sqrtf(s2) * rsqrtf(s2 + EPSQ);
        __syncthreads();
        if (tid == 0) {
            int bm = 0; float mx = nrm[0];
            for (int jj = 1; jj < 10; jj++)
                if (nrm[jj] > mx) { mx = nrm[jj]; bm = jj; }
            amax = bm;
        }
        if (d == 0) dout[b * 10 + j] = nrm[j];
        __syncthreads();
        g_masked[b * 160 + tid] = (j == amax) ? v : 0.f;
    }
}

// ---------------- decoder FC: act 1=relu, 2=sigmoid ----------------
__global__ void fc_kernel(const float* __restrict__ in, const float* __restrict__ W,
                          const float* __restrict__ bias, float* __restrict__ out,
                          int IN, int OUT, int act) {
    int gid = blockIdx.x * blockDim.x + threadIdx.x;
    if (gid >= BATCH * OUT) return;
    int o = gid % OUT, b = gid / OUT;
    const float* ip = in + (size_t)b * IN;
    float acc = bias[o];
    for (int k = 0; k < IN; k++) acc += ip[k] * W[(size_t)k * OUT + o];
    if (act == 1) acc = fmaxf(acc, 0.f);
    else          acc = 1.f / (1.f + __expf(-acc));
    out[gid] = acc;
}

// ---------------- launch ----------------
extern "C" void kernel_launch(void* const* d_in, const int* in_sizes, int n_in,
                              void* d_out, int out_size) {
    const float* x   = (const float*)d_in[0];
    const float* c1w = (const float*)d_in[1];
    const float* c1b = (const float*)d_in[2];
    const float* c2w = (const float*)d_in[3];
    const float* c2b = (const float*)d_in[4];
    const float* pcw = (const float*)d_in[5];
    const float* pcb = (const float*)d_in[6];
    const float* Wc  = (const float*)d_in[7];
    const float* w1  = (const float*)d_in[8];
    const float* b1  = (const float*)d_in[9];
    const float* w2  = (const float*)d_in[10];
    const float* b2  = (const float*)d_in[11];
    const float* w3  = (const float*)d_in[12];
    const float* b3  = (const float*)d_in[13];
    float* dout = (float*)d_out;

    float *p_c1, *p_c2, *p_p, *p_w2t, *p_wpt, *p_s, *p_V, *p_masked, *p_d1, *p_d2;
    cudaGetSymbolAddress((void**)&p_c1, g_c1);
    cudaGetSymbolAddress((void**)&p_c2, g_c2);
    cudaGetSymbolAddress((void**)&p_p,  g_p);
    cudaGetSymbolAddress((void**)&p_w2t, g_w2t);
    cudaGetSymbolAddress((void**)&p_wpt, g_wpt);
    cudaGetSymbolAddress((void**)&p_s,  g_s);
    cudaGetSymbolAddress((void**)&p_V,  g_V);
    cudaGetSymbolAddress((void**)&p_masked, g_masked);
    cudaGetSymbolAddress((void**)&p_d1, g_d1);
    cudaGetSymbolAddress((void**)&p_d2, g_d2);

    // weight pre-transposition (coalesced conv weight loads)
    transform_w_kernel<<<(256 * 256 * 25 + 255) / 256, 256>>>(c2w, p_w2t, 256, 25);
    transform_w_kernel<<<(256 * 256 * 81 + 255) / 256, 256>>>(pcw, p_wpt, 256, 81);

    // conv1: (16,1,64,64) -> (16,256,56,56), relu
    conv1_kernel<<<dim3(16, 8, 16), 196>>>(x, c1w, c1b, p_c1);

    // conv2: (16,256,56,56) -> (16,256,52,52), relu
    conv_tile_kernel<256, 5, 5, 56, 56, 52, 52, 1, 4, true>
        <<<dim3(49, 4, 16), 256>>>(p_c1, p_w2t, c2b, p_c2);

    // primary caps conv: (16,256,52,52) -> (16,256,22,22), stride 2, no relu
    conv_tile_kernel<256, 9, 9, 52, 52, 22, 22, 2, 1, false>
        <<<dim3(9, 4, 16), 256>>>(p_c2, p_wpt, pcb, p_p);

    squash_u_kernel<<<(BATCH * NI + 255) / 256, 256>>>();
    uhat_kernel<<<((size_t)NI * 160 + 255) / 256, 256>>>(Wc);

    cudaMemsetAsync(p_V, 0, BATCH * 160 * sizeof(float));
    for (int r = 0; r < 3; r++) {
        cudaMemsetAsync(p_s, 0, BATCH * 160 * sizeof(float));
        routing_s_kernel<<<dim3(32, 16), 256>>>();
        v_update_kernel<<<16, 160>>>(r == 2 ? 1 : 0, dout);
    }

    fc_kernel<<<(BATCH * 512 + 255) / 256, 256>>>(p_masked, w1, b1, p_d1, 160, 512, 1);
    fc_kernel<<<(BATCH * 1024 + 255) / 256, 256>>>(p_d1, w2, b2, p_d2, 512, 1024, 1);
    fc_kernel<<<(BATCH * 4096 + 255) / 256, 256>>>(p_d2, w3, b3, dout + 160, 1024, 4096, 2);
}

// round 4
// speedup vs baseline: 2.1226x; 2.1226x over previous
#include <cuda_runtime.h>
#include <cuda_bf16.h>
#include <cstdint>

#define EPSQ 1e-8f

static const int BATCH = 16;
static const int NI = 15488;

// ---------------- scratch (device globals) ----------------
__device__ float g_c1[(size_t)16 * 56 * 56 * 256];     // NHWC
__device__ float g_c2[(size_t)16 * 52 * 52 * 256];     // NHWC
__device__ float g_p [(size_t)16 * 256 * 22 * 22];     // NCHW (capsule flatten order)
__device__ float g_u [(size_t)16 * 15488 * 8];
__device__ float g_uhat[(size_t)16 * 15488 * 10 * 16];
__device__ __nv_bfloat16 g_w2h[(size_t)2 * 100 * 8192];   // [octile][chunk][swizzled 64k x 128n]
__device__ __nv_bfloat16 g_w2l[(size_t)2 * 100 * 8192];
__device__ __nv_bfloat16 g_wph[(size_t)2 * 324 * 8192];
__device__ __nv_bfloat16 g_wpl[(size_t)2 * 324 * 8192];
__device__ float g_s[16 * 160];
__device__ float g_V[16 * 160];
__device__ float g_masked[16 * 160];
__device__ float g_d1[16 * 512];
__device__ float g_d2[16 * 1024];

// ---------------- warp MMA helpers (base-ISA HMMA, compiles for compute_103) ----------------
__device__ __forceinline__ uint32_t smem_to_u32(const void* p) {
    uint32_t a;
    asm("{ .reg .u64 t; cvta.to.shared.u64 t, %1; cvt.u32.u64 %0, t; }" : "=r"(a) : "l"(p));
    return a;
}
__device__ __forceinline__ void ldsm_x4(uint32_t& r0, uint32_t& r1, uint32_t& r2, uint32_t& r3, uint32_t addr) {
    asm volatile("ldmatrix.sync.aligned.m8n8.x4.shared.b16 {%0,%1,%2,%3}, [%4];"
                 : "=r"(r0), "=r"(r1), "=r"(r2), "=r"(r3) : "r"(addr));
}
__device__ __forceinline__ void ldsm_x4_t(uint32_t& r0, uint32_t& r1, uint32_t& r2, uint32_t& r3, uint32_t addr) {
    asm volatile("ldmatrix.sync.aligned.m8n8.x4.trans.shared.b16 {%0,%1,%2,%3}, [%4];"
                 : "=r"(r0), "=r"(r1), "=r"(r2), "=r"(r3) : "r"(addr));
}
__device__ __forceinline__ void mma16816(float* c, const uint32_t* a, const uint32_t* b) {
    asm volatile("mma.sync.aligned.m16n8k16.row.col.f32.bf16.bf16.f32 "
                 "{%0,%1,%2,%3}, {%4,%5,%6,%7}, {%8,%9}, {%0,%1,%2,%3};"
                 : "+f"(c[0]), "+f"(c[1]), "+f"(c[2]), "+f"(c[3])
                 : "r"(a[0]), "r"(a[1]), "r"(a[2]), "r"(a[3]), "r"(b[0]), "r"(b[1]));
}

// ---------------- weight split+swizzle transform ----------------
// B-tile global image: [octile(2)][chunk][64 rows(k=ic) x 128 cols(n=oc) bf16, swizzled]
// chunk = kyx*4 + icq ; ic = icq*64 + k ; swizzle: off ^ (((off>>8)&7)<<4)  (256B rows)
__global__ void transform_wsplit_kernel(const float* __restrict__ w,
                                        __nv_bfloat16* __restrict__ wh,
                                        __nv_bfloat16* __restrict__ wl,
                                        int KH, int KW, int NCHUNK) {
    int idx = blockIdx.x * 256 + threadIdx.x;   // pair index (2 adjacent oc)
    int total = 2 * NCHUNK * 64 * 64;
    if (idx >= total) return;
    int np = idx & 63;                // n pair: n = np*2
    int k  = (idx >> 6) & 63;         // ic within chunk
    int chunk = (idx >> 12) % NCHUNK;
    int octile = idx / (NCHUNK << 12);
    int kyx = chunk >> 2;
    int ic = (chunk & 3) * 64 + k;
    int ky = kyx / KW, kx = kyx % KW;
    int oc = octile * 128 + np * 2;
    size_t KHW = (size_t)KH * KW;
    size_t wi = (((size_t)oc * 256 + ic) * KH + ky) * KW + kx;
    float f0 = w[wi];
    float f1 = w[wi + 256 * KHW];
    __nv_bfloat16 h0 = __float2bfloat16(f0);
    __nv_bfloat16 h1 = __float2bfloat16(f1);
    __nv_bfloat16 l0 = __float2bfloat16(f0 - __bfloat162float(h0));
    __nv_bfloat16 l1 = __float2bfloat16(f1 - __bfloat162float(h1));
    uint32_t hp = ((uint32_t)__bfloat16_as_ushort(h1) << 16) | __bfloat16_as_ushort(h0);
    uint32_t lp = ((uint32_t)__bfloat16_as_ushort(l1) << 16) | __bfloat16_as_ushort(l0);
    int off = k * 256 + np * 4;
    int sw = off ^ (((off >> 8) & 7) << 4);
    size_t tb = (size_t)(octile * NCHUNK + chunk) * 16384;
    *(uint32_t*)((char*)wh + tb + sw) = hp;
    *(uint32_t*)((char*)wl + tb + sw) = lp;
}

// ---------------- conv1: 1->256, 9x9, s1, 64->56, NHWC out ----------------
__global__ __launch_bounds__(196)
void conv1_kernel(const float* __restrict__ x, const float* __restrict__ w,
                  const float* __restrict__ bias, float* __restrict__ out) {
    __shared__ float s_in[22 * 22];
    __shared__ float s_w[4 * 81];
    int tid = threadIdx.x;
    int tileY = blockIdx.x >> 2, tileX = blockIdx.x & 3;
    int b = blockIdx.z;
    int ocg = blockIdx.y;

    for (int idx = tid; idx < 484; idx += 196) {
        int r = idx / 22, cc = idx % 22;
        s_in[idx] = x[((size_t)b * 64 + tileY * 14 + r) * 64 + tileX * 14 + cc];
    }
    int sy = tid / 14, sx = tid % 14;

    for (int oi = 0; oi < 32; oi += 4) {
        __syncthreads();
        for (int idx = tid; idx < 4 * 81; idx += 196) {
            int o = idx / 81, k = idx % 81;
            s_w[idx] = w[(size_t)(ocg * 32 + oi + o) * 81 + k];
        }
        __syncthreads();
        float a0 = 0.f, a1 = 0.f, a2 = 0.f, a3 = 0.f;
        for (int ky = 0; ky < 9; ky++) {
            #pragma unroll
            for (int kx = 0; kx < 9; kx++) {
                float v = s_in[(sy + ky) * 22 + sx + kx];
                int k = ky * 9 + kx;
                a0 += v * s_w[k];
                a1 += v * s_w[81 + k];
                a2 += v * s_w[162 + k];
                a3 += v * s_w[243 + k];
            }
        }
        int oc = ocg * 32 + oi;
        size_t ob = ((size_t)(b * 56 + tileY * 14 + sy) * 56 + tileX * 14 + sx) * 256 + oc;
        float4 v4;
        v4.x = fmaxf(a0 + bias[oc],     0.f);
        v4.y = fmaxf(a1 + bias[oc + 1], 0.f);
        v4.z = fmaxf(a2 + bias[oc + 2], 0.f);
        v4.w = fmaxf(a3 + bias[oc + 3], 0.f);
        *(float4*)(out + ob) = v4;
    }
}

// ---------------- HMMA implicit-GEMM conv (bf16 3-term split) ----------------
// Block: 128 pos (M) x 128 oc (N); 8 warps in 2(M) x 4(N); warp tile 64x32.
// K chunked 64 ic; chunk = (ky*KW+kx)*4 + icq.
// SMEM: A (pos x ic, 128B rows, SW128) hi/lo; B (ic x oc, 256B rows, swizzled) hi/lo.
#define SM_AH 0
#define SM_AL 16384
#define SM_BH 32768
#define SM_BL 49152
#define SMEM_CONV_TOTAL 65536

template<int IH, int IW, int OH, int OW, int KW, int STRIDE, int NCHUNK, int NPOS, bool RELU, bool NHWC_OUT>
__global__ __launch_bounds__(256, 2)
void conv_mma_kernel(const float* __restrict__ in,
                     const __nv_bfloat16* __restrict__ wh,
                     const __nv_bfloat16* __restrict__ wl,
                     const float* __restrict__ bias,
                     float* __restrict__ out) {
    extern __shared__ char smem[];
    const uint32_t sb = smem_to_u32(smem);
    const int tid = threadIdx.x;
    const int wid = tid >> 5, lid = tid & 31;
    const int tile = blockIdx.x, mt = blockIdx.y;

    // gather identity (A fill): row = pos within tile, half = 32-channel half
    const int n_row = tid >> 1;
    const int half = tid & 1;
    const int p_mine = tile * 128 + n_row;
    const bool pvalid = p_mine < NPOS;
    int pb = 0, pr = 0, pcx = 0;
    if (pvalid) {
        pb = p_mine / (OH * OW);
        int rem = p_mine - pb * (OH * OW);
        pr = rem / OW;
        pcx = rem - pr * OW;
    }

    const int wm = wid >> 2, wn = wid & 3;
    const int lane15 = lid & 15, lane16 = lid >> 4;
    const int gid = lid >> 2, tig = lid & 3;

    float acc[4][4][4];
    #pragma unroll
    for (int ma = 0; ma < 4; ma++)
        #pragma unroll
        for (int na = 0; na < 4; na++)
            #pragma unroll
            for (int q = 0; q < 4; q++) acc[ma][na][q] = 0.f;

    const int rbase = (wm * 64 + lane15) * 128;
    const int offB_base = lane15 * 256 + wn * 64 + lane16 * 16;

    for (int chunk = 0; chunk < NCHUNK; ++chunk) {
        // ---- B fill: straight copy of pre-swizzled 16KB hi + 16KB lo ----
        {
            const uint4* sh = (const uint4*)(wh + (size_t)(mt * NCHUNK + chunk) * 8192);
            const uint4* sl = (const uint4*)(wl + (size_t)(mt * NCHUNK + chunk) * 8192);
            uint4* dh = (uint4*)(smem + SM_BH);
            uint4* dl = (uint4*)(smem + SM_BL);
            #pragma unroll
            for (int i = 0; i < 4; i++) {
                dh[tid + i * 256] = sh[tid + i * 256];
                dl[tid + i * 256] = sl[tid + i * 256];
            }
        }
        // ---- A fill: gather NHWC input, split hi/lo bf16, swizzled store ----
        {
            const int kyx = chunk >> 2;
            const int ic0 = (chunk & 3) * 64;
            const int ky = kyx / KW, kx = kyx % KW;
            const float* gp = in;
            if (pvalid) {
                int iy = pr * STRIDE + ky, ix = pcx * STRIDE + kx;
                gp = in + (((size_t)pb * IH + iy) * IW + ix) * 256 + ic0 + half * 32;
            }
            char* ah = smem + SM_AH;
            char* al = smem + SM_AL;
            #pragma unroll
            for (int i = 0; i < 8; i++) {
                float4 f = pvalid ? ((const float4*)gp)[i] : make_float4(0.f, 0.f, 0.f, 0.f);
                __nv_bfloat16 h0 = __float2bfloat16(f.x);
                __nv_bfloat16 h1 = __float2bfloat16(f.y);
                __nv_bfloat16 h2 = __float2bfloat16(f.z);
                __nv_bfloat16 h3 = __float2bfloat16(f.w);
                __nv_bfloat16 l0 = __float2bfloat16(f.x - __bfloat162float(h0));
                __nv_bfloat16 l1 = __float2bfloat16(f.y - __bfloat162float(h1));
                __nv_bfloat16 l2 = __float2bfloat16(f.z - __bfloat162float(h2));
                __nv_bfloat16 l3 = __float2bfloat16(f.w - __bfloat162float(h3));
                uint32_t hA = ((uint32_t)__bfloat16_as_ushort(h1) << 16) | __bfloat16_as_ushort(h0);
                uint32_t hB = ((uint32_t)__bfloat16_as_ushort(h3) << 16) | __bfloat16_as_ushort(h2);
                uint32_t lA = ((uint32_t)__bfloat16_as_ushort(l1) << 16) | __bfloat16_as_ushort(l0);
                uint32_t lB = ((uint32_t)__bfloat16_as_ushort(l3) << 16) | __bfloat16_as_ushort(l2);
                int off0 = n_row * 128 + half * 64 + 8 * i;
                int sw0 = off0 ^ ((off0 >> 3) & 0x70);
                int off1 = off0 + 4;
                int sw1 = off1 ^ ((off1 >> 3) & 0x70);
                *(uint32_t*)(ah + sw0) = hA;
                *(uint32_t*)(al + sw0) = lA;
                *(uint32_t*)(ah + sw1) = hB;
                *(uint32_t*)(al + sw1) = lB;
            }
        }
        __syncthreads();

        // ---- compute: 4 k-steps of m16n8k16, 3-term split ----
        #pragma unroll
        for (int ks = 0; ks < 4; ks++) {
            uint32_t Bh[4][2], Bl[4][2];
            #pragma unroll
            for (int np = 0; np < 2; np++) {
                int off = offB_base + ks * 16 * 256 + np * 32;
                int sw = off ^ (((off >> 8) & 7) << 4);
                ldsm_x4_t(Bh[np * 2][0], Bh[np * 2][1], Bh[np * 2 + 1][0], Bh[np * 2 + 1][1], sb + SM_BH + sw);
                ldsm_x4_t(Bl[np * 2][0], Bl[np * 2][1], Bl[np * 2 + 1][0], Bl[np * 2 + 1][1], sb + SM_BL + sw);
            }
            const int cbA = ks * 32 + lane16 * 16;
            #pragma unroll
            for (int ma = 0; ma < 4; ma++) {
                int offA = rbase + ma * 2048 + cbA;
                int swA = offA ^ ((offA >> 3) & 0x70);
                uint32_t a[4];
                ldsm_x4(a[0], a[1], a[2], a[3], sb + SM_AH + swA);
                #pragma unroll
                for (int na = 0; na < 4; na++) mma16816(acc[ma][na], a, Bh[na]);
                #pragma unroll
                for (int na = 0; na < 4; na++) mma16816(acc[ma][na], a, Bl[na]);
                ldsm_x4(a[0], a[1], a[2], a[3], sb + SM_AL + swA);
                #pragma unroll
                for (int na = 0; na < 4; na++) mma16816(acc[ma][na], a, Bh[na]);
            }
        }
        __syncthreads();
    }

    // ---- epilogue: bias (+relu) and store ----
    #pragma unroll
    for (int ma = 0; ma < 4; ma++) {
        #pragma unroll
        for (int h = 0; h < 2; h++) {
            int p = tile * 128 + wm * 64 + ma * 16 + h * 8 + gid;
            if (p >= NPOS) continue;
            if (NHWC_OUT) {
                float* op = out + (size_t)p * 256;
                #pragma unroll
                for (int na = 0; na < 4; na++) {
                    int oc = mt * 128 + wn * 32 + na * 8 + tig * 2;
                    float v0 = acc[ma][na][h * 2 + 0] + bias[oc];
                    float v1 = acc[ma][na][h * 2 + 1] + bias[oc + 1];
                    if (RELU) { v0 = fmaxf(v0, 0.f); v1 = fmaxf(v1, 0.f); }
                    op[oc] = v0;
                    op[oc + 1] = v1;
                }
            } else {
                int b = p / (OH * OW);
                int rem = p - b * (OH * OW);
                int rr = rem / OW;
                int cx = rem - rr * OW;
                size_t base = ((size_t)b * 256) * OH * OW + (size_t)rr * OW + cx;
                #pragma unroll
                for (int na = 0; na < 4; na++) {
                    int oc = mt * 128 + wn * 32 + na * 8 + tig * 2;
                    float v0 = acc[ma][na][h * 2 + 0] + bias[oc];
                    float v1 = acc[ma][na][h * 2 + 1] + bias[oc + 1];
                    if (RELU) { v0 = fmaxf(v0, 0.f); v1 = fmaxf(v1, 0.f); }
                    out[base + (size_t)oc * OH * OW] = v0;
                    out[base + (size_t)(oc + 1) * OH * OW] = v1;
                }
            }
        }
    }
}

// ---------------- squash primary caps: p -> u ----------------
__global__ void squash_u_kernel() {
    int cap = blockIdx.x * 256 + threadIdx.x;
    if (cap >= BATCH * NI) return;
    const float4* pp = (const float4*)(g_p + (size_t)cap * 8);
    float4 a = pp[0], c = pp[1];
    float s2 = a.x * a.x + a.y * a.y + a.z * a.z + a.w * a.w
             + c.x * c.x + c.y * c.y + c.z * c.z + c.w * c.w;
    float f = s2 / (1.f + s2) * rsqrtf(s2 + EPSQ);
    a.x *= f; a.y *= f; a.z *= f; a.w *= f;
    c.x *= f; c.y *= f; c.z *= f; c.w *= f;
    float4* uo = (float4*)(g_u + (size_t)cap * 8);
    uo[0] = a; uo[1] = c;
}

// ---------------- u_hat ----------------
__global__ __launch_bounds__(256)
void uhat_kernel(const float* __restrict__ W) {
    int gid = blockIdx.x * 256 + threadIdx.x;
    int d = gid & 15;
    int j = (gid >> 4) % 10;
    int i = gid / 160;
    if (i >= NI) return;
    const float4* Wp = (const float4*)(W + (((size_t)j * NI + i) * 16 + d) * 8);
    float4 w0 = Wp[0], w1 = Wp[1];
    for (int b = 0; b < BATCH; b++) {
        const float4* up = (const float4*)(g_u + ((size_t)b * NI + i) * 8);
        float4 u0 = up[0], u1 = up[1];
        float acc = w0.x * u0.x + w0.y * u0.y + w0.z * u0.z + w0.w * u0.w
                  + w1.x * u1.x + w1.y * u1.y + w1.z * u1.z + w1.w * u1.w;
        g_uhat[(((size_t)b * NI + i) * 10 + j) * 16 + d] = acc;
    }
}

// ---------------- routing ----------------
__global__ __launch_bounds__(256)
void routing_s_kernel() {
    __shared__ float Vsh[160];
    __shared__ float ssh[160];
    int tid = threadIdx.x;
    int b = blockIdx.y;
    if (tid < 160) { Vsh[tid] = g_V[b * 160 + tid]; ssh[tid] = 0.f; }
    __syncthreads();
    int d = tid & 15, il = tid >> 4;
    float accj[10];
    #pragma unroll
    for (int j = 0; j < 10; j++) accj[j] = 0.f;

    const int per = NI / 32;
    int i0 = blockIdx.x * per;
    for (int i = i0 + il; i < i0 + per; i += 16) {
        const float* uh = g_uhat + (((size_t)b * NI + i) * 10) * 16 + d;
        float uv[10], e[10];
        float m = -1e30f;
        #pragma unroll
        for (int j = 0; j < 10; j++) {
            uv[j] = uh[j * 16];
            float l = uv[j] * Vsh[j * 16 + d];
            e[j] = l;
            m = fmaxf(m, l);
        }
        float se = 0.f;
        #pragma unroll
        for (int j = 0; j < 10; j++) { e[j] = __expf(e[j] - m); se += e[j]; }
        float inv = 1.f / se;
        #pragma unroll
        for (int j = 0; j < 10; j++) accj[j] += e[j] * inv * uv[j];
    }
    #pragma unroll
    for (int j = 0; j < 10; j++) atomicAdd(&ssh[j * 16 + d], accj[j]);
    __syncthreads();
    if (tid < 160) atomicAdd(&g_s[b * 160 + tid], ssh[tid]);
}

// ---------------- v update / final ----------------
__global__ void v_update_kernel(int last, float* __restrict__ dout) {
    __shared__ float s2sh[10];
    __shared__ float nrm[10];
    __shared__ int amax;
    int b = blockIdx.x, tid = threadIdx.x;
    int j = tid >> 4, d = tid & 15;
    if (tid < 10) s2sh[tid] = 0.f;
    __syncthreads();
    float sv = g_s[b * 160 + tid];
    atomicAdd(&s2sh[j], sv * sv);
    __syncthreads();
    float s2 = s2sh[j];
    float v = s2 / (1.f + s2) * sv * rsqrtf(s2 + EPSQ);
    if (!last) {
        g_V[b * 160 + tid] += v;
    } else {
        if (d == 0) nrm[j] = s2 / (1.f + s2) * sqrtf(s2) * rsqrtf(s2 + EPSQ);
        __syncthreads();
        if (tid == 0) {
            int bm = 0; float mx = nrm[0];
            for (int jj = 1; jj < 10; jj++)
                if (nrm[jj] > mx) { mx = nrm[jj]; bm = jj; }
            amax = bm;
        }
        if (d == 0) dout[b * 10 + j] = nrm[j];
        __syncthreads();
        g_masked[b * 160 + tid] = (j == amax) ? v : 0.f;
    }
}

// ---------------- decoder FC ----------------
__global__ void fc_kernel(const float* __restrict__ in, const float* __restrict__ W,
                          const float* __restrict__ bias, float* __restrict__ out,
                          int IN, int OUT, int act) {
    int gid = blockIdx.x * blockDim.x + threadIdx.x;
    if (gid >= BATCH * OUT) return;
    int o = gid % OUT, b = gid / OUT;
    const float* ip = in + (size_t)b * IN;
    float acc = bias[o];
    for (int k = 0; k < IN; k++) acc += ip[k] * W[(size_t)k * OUT + o];
    if (act == 1) acc = fmaxf(acc, 0.f);
    else          acc = 1.f / (1.f + __expf(-acc));
    out[gid] = acc;
}

// ---------------- launch ----------------
extern "C" void kernel_launch(void* const* d_in, const int* in_sizes, int n_in,
                              void* d_out, int out_size) {
    const float* x   = (const float*)d_in[0];
    const float* c1w = (const float*)d_in[1];
    const float* c1b = (const float*)d_in[2];
    const float* c2w = (const float*)d_in[3];
    const float* c2b = (const float*)d_in[4];
    const float* pcw = (const float*)d_in[5];
    const float* pcb = (const float*)d_in[6];
    const float* Wc  = (const float*)d_in[7];
    const float* w1  = (const float*)d_in[8];
    const float* b1  = (const float*)d_in[9];
    const float* w2  = (const float*)d_in[10];
    const float* b2  = (const float*)d_in[11];
    const float* w3  = (const float*)d_in[12];
    const float* b3  = (const float*)d_in[13];
    float* dout = (float*)d_out;

    float *p_c1, *p_c2, *p_p, *p_s, *p_V, *p_masked, *p_d1, *p_d2;
    __nv_bfloat16 *p_w2h, *p_w2l, *p_wph, *p_wpl;
    cudaGetSymbolAddress((void**)&p_c1, g_c1);
    cudaGetSymbolAddress((void**)&p_c2, g_c2);
    cudaGetSymbolAddress((void**)&p_p,  g_p);
    cudaGetSymbolAddress((void**)&p_w2h, g_w2h);
    cudaGetSymbolAddress((void**)&p_w2l, g_w2l);
    cudaGetSymbolAddress((void**)&p_wph, g_wph);
    cudaGetSymbolAddress((void**)&p_wpl, g_wpl);
    cudaGetSymbolAddress((void**)&p_s,  g_s);
    cudaGetSymbolAddress((void**)&p_V,  g_V);
    cudaGetSymbolAddress((void**)&p_masked, g_masked);
    cudaGetSymbolAddress((void**)&p_d1, g_d1);
    cudaGetSymbolAddress((void**)&p_d2, g_d2);

    // conv2: IH=56 OH=52 KW=5 S=1 NCHUNK=100 NPOS=43264, relu, NHWC out
    auto conv2 = conv_mma_kernel<56, 56, 52, 52, 5, 1, 100, 43264, true, true>;
    // pc: IH=52 OH=22 KW=9 S=2 NCHUNK=324 NPOS=7744, no relu, NCHW out
    auto convp = conv_mma_kernel<52, 52, 22, 22, 9, 2, 324, 7744, false, false>;
    cudaFuncSetAttribute(conv2, cudaFuncAttributeMaxDynamicSharedMemorySize, SMEM_CONV_TOTAL);
    cudaFuncSetAttribute(convp, cudaFuncAttributeMaxDynamicSharedMemorySize, SMEM_CONV_TOTAL);

    // weight split/swizzle transforms
    transform_wsplit_kernel<<<(2 * 100 * 4096 + 255) / 256, 256>>>(c2w, p_w2h, p_w2l, 5, 5, 100);
    transform_wsplit_kernel<<<(2 * 324 * 4096 + 255) / 256, 256>>>(pcw, p_wph, p_wpl, 9, 9, 324);

    // conv1 (NHWC out)
    conv1_kernel<<<dim3(16, 8, 16), 196>>>(x, c1w, c1b, p_c1);

    // conv2 + primary caps via HMMA
    conv2<<<dim3(338, 2), 256, SMEM_CONV_TOTAL>>>(p_c1, p_w2h, p_w2l, c2b, p_c2);
    convp<<<dim3(61, 2), 256, SMEM_CONV_TOTAL>>>(p_c2, p_wph, p_wpl, pcb, p_p);

    squash_u_kernel<<<(BATCH * NI + 255) / 256, 256>>>();
    uhat_kernel<<<((size_t)NI * 160 + 255) / 256, 256>>>(Wc);

    cudaMemsetAsync(p_V, 0, BATCH * 160 * sizeof(float));
    for (int r = 0; r < 3; r++) {
        cudaMemsetAsync(p_s, 0, BATCH * 160 * sizeof(float));
        routing_s_kernel<<<dim3(32, 16), 256>>>();
        v_update_kernel<<<16, 160>>>(r == 2 ? 1 : 0, dout);
    }

    fc_kernel<<<(BATCH * 512 + 255) / 256, 256>>>(p_masked, w1, b1, p_d1, 160, 512, 1);
    fc_kernel<<<(BATCH * 1024 + 255) / 256, 256>>>(p_d1, w2, b2, p_d2, 512, 1024, 1);
    fc_kernel<<<(BATCH * 4096 + 255) / 256, 256>>>(p_d2, w3, b3, dout + 160, 1024, 4096, 2);
}

// round 5
// speedup vs baseline: 3.4461x; 1.6236x over previous
#include <cuda_runtime.h>
#include <cuda_bf16.h>
#include <cstdint>

#define EPSQ 1e-8f

static const int BATCH = 16;
static const int NI = 15488;

// ---------------- scratch (device globals) ----------------
__device__ __nv_bfloat16 g_c1h[(size_t)16 * 56 * 56 * 256];   // NHWC hi
__device__ __nv_bfloat16 g_c1l[(size_t)16 * 56 * 56 * 256];   // NHWC lo
__device__ __nv_bfloat16 g_c2h[(size_t)16 * 52 * 52 * 256];
__device__ __nv_bfloat16 g_c2l[(size_t)16 * 52 * 52 * 256];
__device__ float g_part[(size_t)2 * 43264 * 256];             // split-K partials (reused)
__device__ float g_p [(size_t)16 * 256 * 22 * 22];            // NCHW
__device__ float g_u [(size_t)16 * 15488 * 8];
__device__ __nv_bfloat16 g_uhatb[(size_t)16 * 15488 * 10 * 16];
__device__ __nv_bfloat16 g_w2h[(size_t)100 * 16384];          // [chunk][64k x 256n swizzled]
__device__ __nv_bfloat16 g_w2l[(size_t)100 * 16384];
__device__ __nv_bfloat16 g_wph[(size_t)324 * 16384];
__device__ __nv_bfloat16 g_wpl[(size_t)324 * 16384];
__device__ float g_s[16 * 160];
__device__ float g_V[16 * 160];
__device__ float g_masked[16 * 160];
__device__ float g_d1[16 * 512];
__device__ float g_d2[16 * 1024];

// ---------------- PTX helpers (base-ISA, compiles for compute_103) ----------------
__device__ __forceinline__ uint32_t smem_to_u32(const void* p) {
    uint32_t a;
    asm("{ .reg .u64 t; cvta.to.shared.u64 t, %1; cvt.u32.u64 %0, t; }" : "=r"(a) : "l"(p));
    return a;
}
__device__ __forceinline__ void ldsm_x4(uint32_t& r0, uint32_t& r1, uint32_t& r2, uint32_t& r3, uint32_t addr) {
    asm volatile("ldmatrix.sync.aligned.m8n8.x4.shared.b16 {%0,%1,%2,%3}, [%4];"
                 : "=r"(r0), "=r"(r1), "=r"(r2), "=r"(r3) : "r"(addr));
}
__device__ __forceinline__ void ldsm_x4_t(uint32_t& r0, uint32_t& r1, uint32_t& r2, uint32_t& r3, uint32_t addr) {
    asm volatile("ldmatrix.sync.aligned.m8n8.x4.trans.shared.b16 {%0,%1,%2,%3}, [%4];"
                 : "=r"(r0), "=r"(r1), "=r"(r2), "=r"(r3) : "r"(addr));
}
__device__ __forceinline__ void mma16816(float* c, const uint32_t* a, const uint32_t* b) {
    asm volatile("mma.sync.aligned.m16n8k16.row.col.f32.bf16.bf16.f32 "
                 "{%0,%1,%2,%3}, {%4,%5,%6,%7}, {%8,%9}, {%0,%1,%2,%3};"
                 : "+f"(c[0]), "+f"(c[1]), "+f"(c[2]), "+f"(c[3])
                 : "r"(a[0]), "r"(a[1]), "r"(a[2]), "r"(a[3]), "r"(b[0]), "r"(b[1]));
}
#define CP_ASYNC16(dst, src, sz) \
    asm volatile("cp.async.cg.shared.global [%0], [%1], 16, %2;" :: "r"(dst), "l"(src), "r"(sz))
#define CP_COMMIT() asm volatile("cp.async.commit_group;" ::: "memory")
#define CP_WAIT(n)  asm volatile("cp.async.wait_group %0;" :: "n"(n) : "memory")

// ---------------- weight split+swizzle transform ----------------
// image: [chunk][64 rows(k=ic) x 256 cols(n=oc) bf16, swizzled (512B rows, XOR (k&7)<<4)]
__global__ void transform_wsplit_kernel(const float* __restrict__ w,
                                        __nv_bfloat16* __restrict__ wh,
                                        __nv_bfloat16* __restrict__ wl,
                                        int KH, int KW, int NCHUNK) {
    int idx = blockIdx.x * 256 + threadIdx.x;    // n-pair index
    int total = NCHUNK * 64 * 128;
    if (idx >= total) return;
    int np = idx & 127;            // n = np*2
    int k  = (idx >> 7) & 63;      // ic within chunk
    int chunk = idx >> 13;
    int kyx = chunk >> 2;
    int ic = (chunk & 3) * 64 + k;
    int ky = kyx / KW, kx = kyx % KW;
    int oc = np * 2;
    size_t KHW = (size_t)KH * KW;
    size_t wi = (((size_t)oc * 256 + ic) * KH + ky) * KW + kx;
    float f0 = w[wi];
    float f1 = w[wi + 256 * KHW];
    __nv_bfloat16 h0 = __float2bfloat16(f0);
    __nv_bfloat16 h1 = __float2bfloat16(f1);
    __nv_bfloat16 l0 = __float2bfloat16(f0 - __bfloat162float(h0));
    __nv_bfloat16 l1 = __float2bfloat16(f1 - __bfloat162float(h1));
    uint32_t hp = ((uint32_t)__bfloat16_as_ushort(h1) << 16) | __bfloat16_as_ushort(h0);
    uint32_t lp = ((uint32_t)__bfloat16_as_ushort(l1) << 16) | __bfloat16_as_ushort(l0);
    int off = k * 512 + np * 4;
    int sw = off ^ ((k & 7) << 4);
    size_t tb = (size_t)chunk * 32768;
    *(uint32_t*)((char*)wh + tb + sw) = hp;
    *(uint32_t*)((char*)wl + tb + sw) = lp;
}

// ---------------- conv1: 1->256, 9x9, s1, 64->56, NHWC bf16 hi/lo out ----------------
__global__ __launch_bounds__(196)
void conv1_kernel(const float* __restrict__ x, const float* __restrict__ w,
                  const float* __restrict__ bias,
                  __nv_bfloat16* __restrict__ oh, __nv_bfloat16* __restrict__ ol) {
    __shared__ float s_in[22 * 22];
    __shared__ float s_w[4 * 81];
    int tid = threadIdx.x;
    int tileY = blockIdx.x >> 2, tileX = blockIdx.x & 3;
    int b = blockIdx.z;
    int ocg = blockIdx.y;

    for (int idx = tid; idx < 484; idx += 196) {
        int r = idx / 22, cc = idx % 22;
        s_in[idx] = x[((size_t)b * 64 + tileY * 14 + r) * 64 + tileX * 14 + cc];
    }
    int sy = tid / 14, sx = tid % 14;

    for (int oi = 0; oi < 32; oi += 4) {
        __syncthreads();
        for (int idx = tid; idx < 4 * 81; idx += 196) {
            int o = idx / 81, k = idx % 81;
            s_w[idx] = w[(size_t)(ocg * 32 + oi + o) * 81 + k];
        }
        __syncthreads();
        float a0 = 0.f, a1 = 0.f, a2 = 0.f, a3 = 0.f;
        for (int ky = 0; ky < 9; ky++) {
            #pragma unroll
            for (int kx = 0; kx < 9; kx++) {
                float v = s_in[(sy + ky) * 22 + sx + kx];
                int k = ky * 9 + kx;
                a0 += v * s_w[k];
                a1 += v * s_w[81 + k];
                a2 += v * s_w[162 + k];
                a3 += v * s_w[243 + k];
            }
        }
        int oc = ocg * 32 + oi;
        size_t ob = ((size_t)(b * 56 + tileY * 14 + sy) * 56 + tileX * 14 + sx) * 256 + oc;
        float v[4];
        v[0] = fmaxf(a0 + bias[oc],     0.f);
        v[1] = fmaxf(a1 + bias[oc + 1], 0.f);
        v[2] = fmaxf(a2 + bias[oc + 2], 0.f);
        v[3] = fmaxf(a3 + bias[oc + 3], 0.f);
        ushort hh[4], ll[4];
        #pragma unroll
        for (int q = 0; q < 4; q++) {
            __nv_bfloat16 h = __float2bfloat16(v[q]);
            __nv_bfloat16 l = __float2bfloat16(v[q] - __bfloat162float(h));
            hh[q] = __bfloat16_as_ushort(h);
            ll[q] = __bfloat16_as_ushort(l);
        }
        uint2 hp = make_uint2(((uint32_t)hh[1] << 16) | hh[0], ((uint32_t)hh[3] << 16) | hh[2]);
        uint2 lp = make_uint2(((uint32_t)ll[1] << 16) | ll[0], ((uint32_t)ll[3] << 16) | ll[2]);
        *(uint2*)(oh + ob) = hp;
        *(uint2*)(ol + ob) = lp;
    }
}

// ---------------- HMMA implicit-GEMM conv, 2-stage cp.async pipeline ----------------
// Block: 512 thr (16 warps, 4Mx4N); tile M=128 pos x N=256 oc; warp tile 32x64.
// K chunk 64 ic; split-K across blockIdx.y. Partial fp32 out [ksp][p*256+oc].
// SMEM stage (96KB): Ah 16K | Al 16K | Bh 32K | Bl 32K. 2 stages.
#define STG_STRIDE 98304
#define SMEM_CONV_TOTAL (2 * STG_STRIDE)

template<int IH, int IW, int OH, int OW, int KW, int STRIDE, int NCHUNK, int KSPLIT, int NPOS>
__global__ __launch_bounds__(512, 1)
void conv_mma_kernel(const __nv_bfloat16* __restrict__ inh,
                     const __nv_bfloat16* __restrict__ inl,
                     const __nv_bfloat16* __restrict__ wh,
                     const __nv_bfloat16* __restrict__ wl,
                     float* __restrict__ part) {
    extern __shared__ char smem[];
    const uint32_t sb = smem_to_u32(smem);
    const int tid = threadIdx.x;
    const int wid = tid >> 5, lid = tid & 31;
    const int tile = blockIdx.x;

    // A fill identity: row r = tid>>2 (0..127), sp = tid&3 (2 x 16B segs each)
    const int r = tid >> 2, sp = tid & 3;
    const int p_mine = tile * 128 + r;
    const bool pvalid = p_mine < NPOS;
    int pb = 0, pr = 0, pcx = 0;
    if (pvalid) {
        pb = p_mine / (OH * OW);
        int rem = p_mine - pb * (OH * OW);
        pr = rem / OW;
        pcx = rem - pr * OW;
    }
    const int asz = pvalid ? 16 : 0;

    const int wm = wid >> 2, wn = wid & 3;
    const int lane15 = lid & 15, lane16 = lid >> 4;
    const int gid = lid >> 2, tig = lid & 3;

    float acc[2][8][4];
    #pragma unroll
    for (int ma = 0; ma < 2; ma++)
        #pragma unroll
        for (int na = 0; na < 8; na++)
            #pragma unroll
            for (int q = 0; q < 4; q++) acc[ma][na][q] = 0.f;

    const int NC = NCHUNK / KSPLIT;
    const int coff = blockIdx.y * NC;

    auto fill = [&](int stage, int chunk) {
        uint32_t s0 = sb + stage * STG_STRIDE;
        // B: straight copy of pre-swizzled 32KB hi + 32KB lo
        const char* bh = (const char*)(wh + (size_t)chunk * 16384);
        const char* bl = (const char*)(wl + (size_t)chunk * 16384);
        #pragma unroll
        for (int i = 0; i < 4; i++) {
            uint32_t u = (tid + i * 512) * 16;
            CP_ASYNC16(s0 + 32768 + u, bh + u, 16);
            CP_ASYNC16(s0 + 65536 + u, bl + u, 16);
        }
        // A: gather NHWC bf16 rows (64 ch = 128B hi + 128B lo)
        const int kyx = chunk >> 2;
        const int ic0 = (chunk & 3) * 64;
        const int ky = kyx / KW, kx = kyx % KW;
        size_t srcbase = 0;
        if (pvalid) {
            int iy = pr * STRIDE + ky, ix = pcx * STRIDE + kx;
            srcbase = (((size_t)pb * IH + iy) * IW + ix) * 256 + ic0;
        }
        #pragma unroll
        for (int q = 0; q < 2; q++) {
            int seg = sp * 2 + q;
            uint32_t off = r * 128 + seg * 16;
            uint32_t sw = off ^ ((r & 7) << 4);
            CP_ASYNC16(s0 + sw,         (const char*)(inh + srcbase + seg * 8), asz);
            CP_ASYNC16(s0 + 16384 + sw, (const char*)(inl + srcbase + seg * 8), asz);
        }
    };

    fill(0, coff);
    CP_COMMIT();

    for (int i = 0; i < NC; ++i) {
        if (i + 1 < NC) {
            fill((i + 1) & 1, coff + i + 1);
            CP_COMMIT();
            CP_WAIT(1);
        } else {
            CP_WAIT(0);
        }
        __syncthreads();

        const uint32_t s0 = sb + (i & 1) * STG_STRIDE;
        #pragma unroll
        for (int ks = 0; ks < 4; ks++) {
            uint32_t Bh[8][2], Bl[8][2];
            const int brow = ks * 16 + lane15;
            #pragma unroll
            for (int q = 0; q < 4; q++) {
                uint32_t off = brow * 512 + wn * 128 + q * 32 + lane16 * 16;
                uint32_t sw = off ^ ((brow & 7) << 4);
                ldsm_x4_t(Bh[2*q][0], Bh[2*q][1], Bh[2*q+1][0], Bh[2*q+1][1], s0 + 32768 + sw);
                ldsm_x4_t(Bl[2*q][0], Bl[2*q][1], Bl[2*q+1][0], Bl[2*q+1][1], s0 + 65536 + sw);
            }
            #pragma unroll
            for (int ma = 0; ma < 2; ma++) {
                const int arow = wm * 32 + ma * 16 + lane15;
                uint32_t offA = arow * 128 + ks * 32 + lane16 * 16;
                uint32_t swA = offA ^ ((arow & 7) << 4);
                uint32_t a[4];
                ldsm_x4(a[0], a[1], a[2], a[3], s0 + swA);
                #pragma unroll
                for (int na = 0; na < 8; na++) mma16816(acc[ma][na], a, Bh[na]);
                #pragma unroll
                for (int na = 0; na < 8; na++) mma16816(acc[ma][na], a, Bl[na]);
                ldsm_x4(a[0], a[1], a[2], a[3], s0 + 16384 + swA);
                #pragma unroll
                for (int na = 0; na < 8; na++) mma16816(acc[ma][na], a, Bh[na]);
            }
        }
        __syncthreads();
    }

    // ---- epilogue: fp32 partial store ----
    float* op0 = part + (size_t)blockIdx.y * NPOS * 256;
    #pragma unroll
    for (int ma = 0; ma < 2; ma++) {
        #pragma unroll
        for (int h = 0; h < 2; h++) {
            int p = tile * 128 + wm * 32 + ma * 16 + h * 8 + gid;
            if (p >= NPOS) continue;
            float* op = op0 + (size_t)p * 256 + wn * 64 + tig * 2;
            #pragma unroll
            for (int na = 0; na < 8; na++) {
                *(float2*)(op + na * 8) = make_float2(acc[ma][na][h * 2], acc[ma][na][h * 2 + 1]);
            }
        }
    }
}

// ---------------- reduce conv2 partials -> bias+relu -> bf16 hi/lo NHWC ----------------
__global__ void reduce2_kernel(const float* __restrict__ part, const float* __restrict__ bias,
                               __nv_bfloat16* __restrict__ oh, __nv_bfloat16* __restrict__ ol) {
    size_t gid = (size_t)blockIdx.x * 256 + threadIdx.x;   // over 43264*128 pairs
    if (gid >= (size_t)43264 * 128) return;
    int p = (int)(gid >> 7);
    int oc = ((int)gid & 127) * 2;
    const float* p0 = part + (size_t)p * 256 + oc;
    const size_t half = (size_t)43264 * 256;
    float v0 = fmaxf(p0[0] + p0[half]     + bias[oc],     0.f);
    float v1 = fmaxf(p0[1] + p0[half + 1] + bias[oc + 1], 0.f);
    __nv_bfloat16 h0 = __float2bfloat16(v0);
    __nv_bfloat16 h1 = __float2bfloat16(v1);
    __nv_bfloat16 l0 = __float2bfloat16(v0 - __bfloat162float(h0));
    __nv_bfloat16 l1 = __float2bfloat16(v1 - __bfloat162float(h1));
    size_t o = (size_t)p * 256 + oc;
    *(uint32_t*)(oh + o) = ((uint32_t)__bfloat16_as_ushort(h1) << 16) | __bfloat16_as_ushort(h0);
    *(uint32_t*)(ol + o) = ((uint32_t)__bfloat16_as_ushort(l1) << 16) | __bfloat16_as_ushort(l0);
}

// ---------------- reduce pc partials (4-way) -> bias -> fp32 NCHW ----------------
__global__ void reducep_kernel(const float* __restrict__ part, const float* __restrict__ bias,
                               float* __restrict__ out) {
    int gid = blockIdx.x * 256 + threadIdx.x;   // over 7744*256
    if (gid >= 7744 * 256) return;
    int p = gid >> 8, oc = gid & 255;
    const size_t seg = (size_t)7744 * 256;
    const float* p0 = part + (size_t)p * 256 + oc;
    float v = p0[0] + p0[seg] + p0[2 * seg] + p0[3 * seg] + bias[oc];
    int b = p / 484;
    int rem = p - b * 484;
    int rr = rem / 22, cx = rem - rr * 22;
    out[(((size_t)b * 256 + oc) * 22 + rr) * 22 + cx] = v;
}

// ---------------- squash primary caps: p -> u ----------------
__global__ void squash_u_kernel() {
    int cap = blockIdx.x * 256 + threadIdx.x;
    if (cap >= BATCH * NI) return;
    const float4* pp = (const float4*)(g_p + (size_t)cap * 8);
    float4 a = pp[0], c = pp[1];
    float s2 = a.x * a.x + a.y * a.y + a.z * a.z + a.w * a.w
             + c.x * c.x + c.y * c.y + c.z * c.z + c.w * c.w;
    float f = s2 / (1.f + s2) * rsqrtf(s2 + EPSQ);
    a.x *= f; a.y *= f; a.z *= f; a.w *= f;
    c.x *= f; c.y *= f; c.z *= f; c.w *= f;
    float4* uo = (float4*)(g_u + (size_t)cap * 8);
    uo[0] = a; uo[1] = c;
}

// ---------------- u_hat (bf16 out) ----------------
__global__ __launch_bounds__(256)
void uhat_kernel(const float* __restrict__ W) {
    int gid = blockIdx.x * 256 + threadIdx.x;
    int d = gid & 15;
    int j = (gid >> 4) % 10;
    int i = gid / 160;
    if (i >= NI) return;
    const float4* Wp = (const float4*)(W + (((size_t)j * NI + i) * 16 + d) * 8);
    float4 w0 = Wp[0], w1 = Wp[1];
    for (int b = 0; b < BATCH; b++) {
        const float4* up = (const float4*)(g_u + ((size_t)b * NI + i) * 8);
        float4 u0 = up[0], u1 = up[1];
        float acc = w0.x * u0.x + w0.y * u0.y + w0.z * u0.z + w0.w * u0.w
                  + w1.x * u1.x + w1.y * u1.y + w1.z * u1.z + w1.w * u1.w;
        g_uhatb[(((size_t)b * NI + i) * 10 + j) * 16 + d] = __float2bfloat16(acc);
    }
}

// ---------------- routing: s[b,j,d] = sum_i softmax_j(u_hat*Vcum) * u_hat ----------------
__global__ __launch_bounds__(256)
void routing_s_kernel() {
    __shared__ float Vsh[160];
    __shared__ float ssh[160];
    int tid = threadIdx.x;
    int b = blockIdx.y;
    if (tid < 160) { Vsh[tid] = g_V[b * 160 + tid]; ssh[tid] = 0.f; }
    __syncthreads();
    int d = tid & 15, il = tid >> 4;
    float accj[10];
    #pragma unroll
    for (int j = 0; j < 10; j++) accj[j] = 0.f;

    const int per = NI / 32;
    int i0 = blockIdx.x * per;
    for (int i = i0 + il; i < i0 + per; i += 16) {
        const __nv_bfloat16* uh = g_uhatb + (((size_t)b * NI + i) * 10) * 16 + d;
        float uv[10], e[10];
        float m = -1e30f;
        #pragma unroll
        for (int j = 0; j < 10; j++) {
            uv[j] = __bfloat162float(uh[j * 16]);
            float l = uv[j] * Vsh[j * 16 + d];
            e[j] = l;
            m = fmaxf(m, l);
        }
        float se = 0.f;
        #pragma unroll
        for (int j = 0; j < 10; j++) { e[j] = __expf(e[j] - m); se += e[j]; }
        float inv = 1.f / se;
        #pragma unroll
        for (int j = 0; j < 10; j++) accj[j] += e[j] * inv * uv[j];
    }
    #pragma unroll
    for (int j = 0; j < 10; j++) atomicAdd(&ssh[j * 16 + d], accj[j]);
    __syncthreads();
    if (tid < 160) atomicAdd(&g_s[b * 160 + tid], ssh[tid]);
}

// ---------------- v update / final ----------------
__global__ void v_update_kernel(int last, float* __restrict__ dout) {
    __shared__ float s2sh[10];
    __shared__ float nrm[10];
    __shared__ int amax;
    int b = blockIdx.x, tid = threadIdx.x;
    int j = tid >> 4, d = tid & 15;
    if (tid < 10) s2sh[tid] = 0.f;
    __syncthreads();
    float sv = g_s[b * 160 + tid];
    atomicAdd(&s2sh[j], sv * sv);
    __syncthreads();
    float s2 = s2sh[j];
    float v = s2 / (1.f + s2) * sv * rsqrtf(s2 + EPSQ);
    if (!last) {
        g_V[b * 160 + tid] += v;
    } else {
        if (d == 0) nrm[j] = s2 / (1.f + s2) * sqrtf(s2) * rsqrtf(s2 + EPSQ);
        __syncthreads();
        if (tid == 0) {
            int bm = 0; float mx = nrm[0];
            for (int jj = 1; jj < 10; jj++)
                if (nrm[jj] > mx) { mx = nrm[jj]; bm = jj; }
            amax = bm;
        }
        if (d == 0) dout[b * 10 + j] = nrm[j];
        __syncthreads();
        g_masked[b * 160 + tid] = (j == amax) ? v : 0.f;
    }
}

// ---------------- decoder FC ----------------
__global__ void fc_kernel(const float* __restrict__ in, const float* __restrict__ W,
                          const float* __restrict__ bias, float* __restrict__ out,
                          int IN, int OUT, int act) {
    int gid = blockIdx.x * blockDim.x + threadIdx.x;
    if (gid >= BATCH * OUT) return;
    int o = gid % OUT, b = gid / OUT;
    const float* ip = in + (size_t)b * IN;
    float acc = bias[o];
    for (int k = 0; k < IN; k++) acc += ip[k] * W[(size_t)k * OUT + o];
    if (act == 1) acc = fmaxf(acc, 0.f);
    else          acc = 1.f / (1.f + __expf(-acc));
    out[gid] = acc;
}

// ---------------- launch ----------------
extern "C" void kernel_launch(void* const* d_in, const int* in_sizes, int n_in,
                              void* d_out, int out_size) {
    const float* x   = (const float*)d_in[0];
    const float* c1w = (const float*)d_in[1];
    const float* c1b = (const float*)d_in[2];
    const float* c2w = (const float*)d_in[3];
    const float* c2b = (const float*)d_in[4];
    const float* pcw = (const float*)d_in[5];
    const float* pcb = (const float*)d_in[6];
    const float* Wc  = (const float*)d_in[7];
    const float* w1  = (const float*)d_in[8];
    const float* b1  = (const float*)d_in[9];
    const float* w2  = (const float*)d_in[10];
    const float* b2  = (const float*)d_in[11];
    const float* w3  = (const float*)d_in[12];
    const float* b3  = (const float*)d_in[13];
    float* dout = (float*)d_out;

    __nv_bfloat16 *p_c1h, *p_c1l, *p_c2h, *p_c2l, *p_w2h, *p_w2l, *p_wph, *p_wpl;
    float *p_part, *p_p, *p_s, *p_V, *p_masked, *p_d1, *p_d2;
    cudaGetSymbolAddress((void**)&p_c1h, g_c1h);
    cudaGetSymbolAddress((void**)&p_c1l, g_c1l);
    cudaGetSymbolAddress((void**)&p_c2h, g_c2h);
    cudaGetSymbolAddress((void**)&p_c2l, g_c2l);
    cudaGetSymbolAddress((void**)&p_part, g_part);
    cudaGetSymbolAddress((void**)&p_p,  g_p);
    cudaGetSymbolAddress((void**)&p_w2h, g_w2h);
    cudaGetSymbolAddress((void**)&p_w2l, g_w2l);
    cudaGetSymbolAddress((void**)&p_wph, g_wph);
    cudaGetSymbolAddress((void**)&p_wpl, g_wpl);
    cudaGetSymbolAddress((void**)&p_s,  g_s);
    cudaGetSymbolAddress((void**)&p_V,  g_V);
    cudaGetSymbolAddress((void**)&p_masked, g_masked);
    cudaGetSymbolAddress((void**)&p_d1, g_d1);
    cudaGetSymbolAddress((void**)&p_d2, g_d2);

    // conv2: IH=56 OH=52 KW=5 S=1 NCHUNK=100 KSPLIT=2 NPOS=43264
    auto conv2 = conv_mma_kernel<56, 56, 52, 52, 5, 1, 100, 2, 43264>;
    // pc: IH=52 OH=22 KW=9 S=2 NCHUNK=324 KSPLIT=4 NPOS=7744
    auto convp = conv_mma_kernel<52, 52, 22, 22, 9, 2, 324, 4, 7744>;
    cudaFuncSetAttribute(conv2, cudaFuncAttributeMaxDynamicSharedMemorySize, SMEM_CONV_TOTAL);
    cudaFuncSetAttribute(convp, cudaFuncAttributeMaxDynamicSharedMemorySize, SMEM_CONV_TOTAL);

    // weight split/swizzle transforms
    transform_wsplit_kernel<<<(100 * 64 * 128 + 255) / 256, 256>>>(c2w, p_w2h, p_w2l, 5, 5, 100);
    transform_wsplit_kernel<<<(324 * 64 * 128 + 255) / 256, 256>>>(pcw, p_wph, p_wpl, 9, 9, 324);

    // conv1 (NHWC bf16 hi/lo out)
    conv1_kernel<<<dim3(16, 8, 16), 196>>>(x, c1w, c1b, p_c1h, p_c1l);

    // conv2: split-K=2 partials, then reduce (bias+relu -> bf16 hi/lo)
    conv2<<<dim3(338, 2), 512, SMEM_CONV_TOTAL>>>(p_c1h, p_c1l, p_w2h, p_w2l, p_part);
    reduce2_kernel<<<(int)(((size_t)43264 * 128 + 255) / 256), 256>>>(p_part, c2b, p_c2h, p_c2l);

    // pc: split-K=4 partials, then reduce (bias -> fp32 NCHW)
    convp<<<dim3(61, 4), 512, SMEM_CONV_TOTAL>>>(p_c2h, p_c2l, p_wph, p_wpl, p_part);
    reducep_kernel<<<(7744 * 256 + 255) / 256, 256>>>(p_part, pcb, p_p);

    squash_u_kernel<<<(BATCH * NI + 255) / 256, 256>>>();
    uhat_kernel<<<((size_t)NI * 160 + 255) / 256, 256>>>(Wc);

    cudaMemsetAsync(p_V, 0, BATCH * 160 * sizeof(float));
    for (int r = 0; r < 3; r++) {
        cudaMemsetAsync(p_s, 0, BATCH * 160 * sizeof(float));
        routing_s_kernel<<<dim3(32, 16), 256>>>();
        v_update_kernel<<<16, 160>>>(r == 2 ? 1 : 0, dout);
    }

    fc_kernel<<<(BATCH * 512 + 255) / 256, 256>>>(p_masked, w1, b1, p_d1, 160, 512, 1);
    fc_kernel<<<(BATCH * 1024 + 255) / 256, 256>>>(p_d1, w2, b2, p_d2, 512, 1024, 1);
    fc_kernel<<<(BATCH * 4096 + 255) / 256, 256>>>(p_d2, w3, b3, dout + 160, 1024, 4096, 2);
}

// round 7
// speedup vs baseline: 3.4475x; 1.0004x over previous
#include <cuda_runtime.h>
#include <cuda_bf16.h>
#include <cstdint>

#define EPSQ 1e-8f

static const int BATCH = 16;
static const int NI = 15488;

// ---------------- scratch (device globals) ----------------
__device__ __nv_bfloat16 g_c1h[(size_t)16 * 56 * 56 * 256];   // NHWC hi
__device__ __nv_bfloat16 g_c1l[(size_t)16 * 56 * 56 * 256];   // NHWC lo
__device__ __nv_bfloat16 g_c2h[(size_t)16 * 52 * 52 * 256];
__device__ __nv_bfloat16 g_c2l[(size_t)16 * 52 * 52 * 256];
__device__ float g_part[(size_t)12 * 7744 * 256];             // pc split-K partials
__device__ float g_p [(size_t)16 * 256 * 22 * 22];            // NCHW
__device__ float g_u [(size_t)16 * 15488 * 8];
__device__ __nv_bfloat16 g_uhatb[(size_t)16 * 15488 * 10 * 16];
__device__ __nv_bfloat16 g_w2h[(size_t)100 * 2 * 8192];       // [chunk][ntile][64k x 128n swz]
__device__ __nv_bfloat16 g_w2l[(size_t)100 * 2 * 8192];
__device__ __nv_bfloat16 g_wph[(size_t)324 * 2 * 8192];
__device__ __nv_bfloat16 g_wpl[(size_t)324 * 2 * 8192];
__device__ float g_s[16 * 160];
__device__ float g_V[16 * 160];
__device__ float g_masked[16 * 160];
__device__ float g_d1[16 * 512];
__device__ float g_d2[16 * 1024];

// ---------------- PTX helpers (base-ISA, compiles for compute_103) ----------------
__device__ __forceinline__ uint32_t smem_to_u32(const void* p) {
    uint32_t a;
    asm("{ .reg .u64 t; cvta.to.shared.u64 t, %1; cvt.u32.u64 %0, t; }" : "=r"(a) : "l"(p));
    return a;
}
__device__ __forceinline__ void ldsm_x4(uint32_t& r0, uint32_t& r1, uint32_t& r2, uint32_t& r3, uint32_t addr) {
    asm volatile("ldmatrix.sync.aligned.m8n8.x4.shared.b16 {%0,%1,%2,%3}, [%4];"
                 : "=r"(r0), "=r"(r1), "=r"(r2), "=r"(r3) : "r"(addr));
}
__device__ __forceinline__ void ldsm_x4_t(uint32_t& r0, uint32_t& r1, uint32_t& r2, uint32_t& r3, uint32_t addr) {
    asm volatile("ldmatrix.sync.aligned.m8n8.x4.trans.shared.b16 {%0,%1,%2,%3}, [%4];"
                 : "=r"(r0), "=r"(r1), "=r"(r2), "=r"(r3) : "r"(addr));
}
__device__ __forceinline__ void mma16816(float* c, const uint32_t* a, const uint32_t* b) {
    asm volatile("mma.sync.aligned.m16n8k16.row.col.f32.bf16.bf16.f32 "
                 "{%0,%1,%2,%3}, {%4,%5,%6,%7}, {%8,%9}, {%0,%1,%2,%3};"
                 : "+f"(c[0]), "+f"(c[1]), "+f"(c[2]), "+f"(c[3])
                 : "r"(a[0]), "r"(a[1]), "r"(a[2]), "r"(a[3]), "r"(b[0]), "r"(b[1]));
}
#define CP_ASYNC16(dst, src, sz) \
    asm volatile("cp.async.cg.shared.global [%0], [%1], 16, %2;" :: "r"(dst), "l"(src), "r"(sz))
#define CP_COMMIT() asm volatile("cp.async.commit_group;" ::: "memory")
#define CP_WAIT(n)  asm volatile("cp.async.wait_group %0;" :: "n"(n) : "memory")

// ---------------- weight split+swizzle transform ----------------
// image: [chunk][ntile(2)][64 rows(k=ic) x 128 cols(n=oc) bf16, 256B rows, XOR (k&7)<<4]
__global__ void transform_wsplit_kernel(const float* __restrict__ w,
                                        __nv_bfloat16* __restrict__ wh,
                                        __nv_bfloat16* __restrict__ wl,
                                        int KH, int KW, int NCHUNK) {
    int idx = blockIdx.x * 256 + threadIdx.x;    // n-pair index
    int total = NCHUNK * 2 * 64 * 64;
    if (idx >= total) return;
    int np = idx & 63;              // n = np*2 within tile
    int k  = (idx >> 6) & 63;       // ic within chunk
    int ntile = (idx >> 12) & 1;
    int chunk = idx >> 13;
    int kyx = chunk >> 2;
    int ic = (chunk & 3) * 64 + k;
    int ky = kyx / KW, kx = kyx % KW;
    int oc = ntile * 128 + np * 2;
    size_t KHW = (size_t)KH * KW;
    size_t wi = (((size_t)oc * 256 + ic) * KH + ky) * KW + kx;
    float f0 = w[wi];
    float f1 = w[wi + 256 * KHW];
    __nv_bfloat16 h0 = __float2bfloat16(f0);
    __nv_bfloat16 h1 = __float2bfloat16(f1);
    __nv_bfloat16 l0 = __float2bfloat16(f0 - __bfloat162float(h0));
    __nv_bfloat16 l1 = __float2bfloat16(f1 - __bfloat162float(h1));
    uint32_t hp = ((uint32_t)__bfloat16_as_ushort(h1) << 16) | __bfloat16_as_ushort(h0);
    uint32_t lp = ((uint32_t)__bfloat16_as_ushort(l1) << 16) | __bfloat16_as_ushort(l0);
    int off = k * 256 + np * 4;
    int sw = off ^ ((k & 7) << 4);
    size_t tb = (size_t)(chunk * 2 + ntile) * 16384;
    *(uint32_t*)((char*)wh + tb + sw) = hp;
    *(uint32_t*)((char*)wl + tb + sw) = lp;
}

// ---------------- conv1: 1->256, 9x9, s1, 64->56, NHWC bf16 hi/lo out ----------------
// 28x28 output tile per CTA; thread = 4 positions x 4 oc register tile.
__global__ __launch_bounds__(196)
void conv1_kernel(const float* __restrict__ x, const float* __restrict__ w,
                  const float* __restrict__ bias,
                  __nv_bfloat16* __restrict__ oh, __nv_bfloat16* __restrict__ ol) {
    __shared__ float s_in[36 * 36];
    __shared__ float s_w[4 * 81];
    int tid = threadIdx.x;
    int tileY = blockIdx.x >> 1, tileX = blockIdx.x & 1;
    int b = blockIdx.z;
    int ocg = blockIdx.y;   // 8 groups of 32 oc

    for (int idx = tid; idx < 1296; idx += 196) {
        int r = idx / 36, cc = idx % 36;
        s_in[idx] = x[((size_t)b * 64 + tileY * 28 + r) * 64 + tileX * 28 + cc];
    }
    int sy = tid / 14, sx = tid % 14;

    for (int oi = 0; oi < 32; oi += 4) {
        __syncthreads();
        for (int idx = tid; idx < 4 * 81; idx += 196) {
            int o = idx / 81, k = idx % 81;
            s_w[idx] = w[(size_t)(ocg * 32 + oi + o) * 81 + k];
        }
        __syncthreads();
        float acc[2][2][4];
        #pragma unroll
        for (int a = 0; a < 2; a++)
            #pragma unroll
            for (int q = 0; q < 2; q++)
                #pragma unroll
                for (int o = 0; o < 4; o++) acc[a][q][o] = 0.f;
        for (int ky = 0; ky < 9; ky++) {
            #pragma unroll
            for (int kx = 0; kx < 9; kx++) {
                int k = ky * 9 + kx;
                float w0 = s_w[k], w1 = s_w[81 + k], w2 = s_w[162 + k], w3 = s_w[243 + k];
                #pragma unroll
                for (int a = 0; a < 2; a++) {
                    #pragma unroll
                    for (int q = 0; q < 2; q++) {
                        float v = s_in[(sy + 14 * a + ky) * 36 + sx + 14 * q + kx];
                        acc[a][q][0] += v * w0;
                        acc[a][q][1] += v * w1;
                        acc[a][q][2] += v * w2;
                        acc[a][q][3] += v * w3;
                    }
                }
            }
        }
        int oc = ocg * 32 + oi;
        float b0 = bias[oc], b1 = bias[oc + 1], b2 = bias[oc + 2], b3 = bias[oc + 3];
        #pragma unroll
        for (int a = 0; a < 2; a++) {
            #pragma unroll
            for (int q = 0; q < 2; q++) {
                int oy = tileY * 28 + a * 14 + sy;
                int ox = tileX * 28 + q * 14 + sx;
                size_t ob = ((size_t)(b * 56 + oy) * 56 + ox) * 256 + oc;
                float v[4];
                v[0] = fmaxf(acc[a][q][0] + b0, 0.f);
                v[1] = fmaxf(acc[a][q][1] + b1, 0.f);
                v[2] = fmaxf(acc[a][q][2] + b2, 0.f);
                v[3] = fmaxf(acc[a][q][3] + b3, 0.f);
                ushort hh[4], ll[4];
                #pragma unroll
                for (int o = 0; o < 4; o++) {
                    __nv_bfloat16 h = __float2bfloat16(v[o]);
                    __nv_bfloat16 l = __float2bfloat16(v[o] - __bfloat162float(h));
                    hh[o] = __bfloat16_as_ushort(h);
                    ll[o] = __bfloat16_as_ushort(l);
                }
                *(uint2*)(oh + ob) = make_uint2(((uint32_t)hh[1] << 16) | hh[0],
                                                ((uint32_t)hh[3] << 16) | hh[2]);
                *(uint2*)(ol + ob) = make_uint2(((uint32_t)ll[1] << 16) | ll[0],
                                                ((uint32_t)ll[3] << 16) | ll[2]);
            }
        }
    }
}

// ---------------- HMMA implicit-GEMM conv, 3-stage cp.async, single sync/chunk ----------------
// Block: 256 thr (8 warps, 4M x 2N); tile M=128 pos x N=128 oc; warp tile 32x64.
// Stage 64KB: Ah 16K | Al 16K | Bh 16K | Bl 16K. 3 stages = 192KB.
#define STG 65536
#define SMEM_CONV_TOTAL (3 * STG)

template<int IH, int IW, int OH, int OW, int KW, int STRIDE, int NCHUNK, int KSPLIT, int NPOS, bool FUSE>
__global__ __launch_bounds__(256, 1)
void conv_mma_kernel(const __nv_bfloat16* __restrict__ inh,
                     const __nv_bfloat16* __restrict__ inl,
                     const __nv_bfloat16* __restrict__ wh,
                     const __nv_bfloat16* __restrict__ wl,
                     const float* __restrict__ bias,
                     __nv_bfloat16* __restrict__ outh,
                     __nv_bfloat16* __restrict__ outl,
                     float* __restrict__ part) {
    extern __shared__ char smem[];
    const uint32_t sb = smem_to_u32(smem);
    const int tid = threadIdx.x;
    const int wid = tid >> 5, lid = tid & 31;
    const int tile = blockIdx.x, ntile = blockIdx.y;

    // A fill identity: row r = tid>>1, sp = tid&1 (4 x 16B segs each)
    const int r = tid >> 1, sp = tid & 1;
    const int p_mine = tile * 128 + r;
    const bool pvalid = p_mine < NPOS;
    int pb = 0, pr = 0, pcx = 0;
    if (pvalid) {
        pb = p_mine / (OH * OW);
        int rem = p_mine - pb * (OH * OW);
        pr = rem / OW;
        pcx = rem - pr * OW;
    }
    const int asz = pvalid ? 16 : 0;

    const int wm = wid >> 1, wn = wid & 1;
    const int lane15 = lid & 15, lane16 = lid >> 4;
    const int gid = lid >> 2, tig = lid & 3;

    float acc[2][8][4];
    #pragma unroll
    for (int ma = 0; ma < 2; ma++)
        #pragma unroll
        for (int na = 0; na < 8; na++)
            #pragma unroll
            for (int q = 0; q < 4; q++) acc[ma][na][q] = 0.f;

    const int NC = NCHUNK / KSPLIT;
    const int coff = blockIdx.z * NC;

    auto fill = [&](int stage, int chunk) {
        uint32_t s0 = sb + stage * STG;
        // B: straight copy of pre-swizzled 16KB hi + 16KB lo
        const char* bh = (const char*)(wh + (size_t)(chunk * 2 + ntile) * 8192);
        const char* bl = (const char*)(wl + (size_t)(chunk * 2 + ntile) * 8192);
        #pragma unroll
        for (int i = 0; i < 4; i++) {
            uint32_t u = (tid + i * 256) * 16;
            CP_ASYNC16(s0 + 32768 + u, bh + u, 16);
            CP_ASYNC16(s0 + 49152 + u, bl + u, 16);
        }
        // A: gather NHWC bf16 rows (64 ch = 128B hi + 128B lo)
        const int kyx = chunk >> 2;
        const int ic0 = (chunk & 3) * 64;
        const int ky = kyx / KW, kx = kyx % KW;
        size_t srcbase = 0;
        if (pvalid) {
            int iy = pr * STRIDE + ky, ix = pcx * STRIDE + kx;
            srcbase = (((size_t)pb * IH + iy) * IW + ix) * 256 + ic0;
        }
        #pragma unroll
        for (int q = 0; q < 4; q++) {
            int seg = sp * 4 + q;
            uint32_t off = r * 128 + seg * 16;
            uint32_t sw = off ^ ((r & 7) << 4);
            CP_ASYNC16(s0 + sw,         (const char*)(inh + srcbase + seg * 8), asz);
            CP_ASYNC16(s0 + 16384 + sw, (const char*)(inl + srcbase + seg * 8), asz);
        }
    };

    fill(0, coff); CP_COMMIT();
    fill(1, coff + 1); CP_COMMIT();

    int st = 0;
    for (int i = 0; i < NC; ++i) {
        if (i < NC - 1) { CP_WAIT(1); } else { CP_WAIT(0); }
        __syncthreads();
        const uint32_t s0 = sb + st * STG;
        #pragma unroll
        for (int ks = 0; ks < 4; ks++) {
            uint32_t Bh[8][2], Bl[8][2];
            const int brow = ks * 16 + lane15;
            #pragma unroll
            for (int q = 0; q < 4; q++) {
                uint32_t off = brow * 256 + wn * 128 + q * 32 + lane16 * 16;
                uint32_t sw = off ^ ((brow & 7) << 4);
                ldsm_x4_t(Bh[2*q][0], Bh[2*q][1], Bh[2*q+1][0], Bh[2*q+1][1], s0 + 32768 + sw);
                ldsm_x4_t(Bl[2*q][0], Bl[2*q][1], Bl[2*q+1][0], Bl[2*q+1][1], s0 + 49152 + sw);
            }
            #pragma unroll
            for (int ma = 0; ma < 2; ma++) {
                const int arow = wm * 32 + ma * 16 + lane15;
                uint32_t offA = arow * 128 + ks * 32 + lane16 * 16;
                uint32_t swA = offA ^ ((arow & 7) << 4);
                uint32_t a[4];
                ldsm_x4(a[0], a[1], a[2], a[3], s0 + swA);
                #pragma unroll
                for (int na = 0; na < 8; na++) mma16816(acc[ma][na], a, Bh[na]);
                #pragma unroll
                for (int na = 0; na < 8; na++) mma16816(acc[ma][na], a, Bl[na]);
                ldsm_x4(a[0], a[1], a[2], a[3], s0 + 16384 + swA);
                #pragma unroll
                for (int na = 0; na < 8; na++) mma16816(acc[ma][na], a, Bh[na]);
            }
        }
        if (i + 2 < NC) { fill((st + 2) % 3, coff + i + 2); CP_COMMIT(); }
        st = (st + 1) % 3;
    }

    // ---- epilogue ----
    if (FUSE) {
        #pragma unroll
        for (int ma = 0; ma < 2; ma++) {
            #pragma unroll
            for (int h = 0; h < 2; h++) {
                int p = tile * 128 + wm * 32 + ma * 16 + h * 8 + gid;
                if (p >= NPOS) continue;
                #pragma unroll
                for (int na = 0; na < 8; na++) {
                    int oc = ntile * 128 + wn * 64 + na * 8 + tig * 2;
                    float v0 = fmaxf(acc[ma][na][h * 2 + 0] + bias[oc],     0.f);
                    float v1 = fmaxf(acc[ma][na][h * 2 + 1] + bias[oc + 1], 0.f);
                    __nv_bfloat16 h0 = __float2bfloat16(v0);
                    __nv_bfloat16 h1 = __float2bfloat16(v1);
                    __nv_bfloat16 l0 = __float2bfloat16(v0 - __bfloat162float(h0));
                    __nv_bfloat16 l1 = __float2bfloat16(v1 - __bfloat162float(h1));
                    size_t o = (size_t)p * 256 + oc;
                    *(uint32_t*)(outh + o) = ((uint32_t)__bfloat16_as_ushort(h1) << 16) | __bfloat16_as_ushort(h0);
                    *(uint32_t*)(outl + o) = ((uint32_t)__bfloat16_as_ushort(l1) << 16) | __bfloat16_as_ushort(l0);
                }
            }
        }
    } else {
        float* op0 = part + (size_t)blockIdx.z * NPOS * 256;
        #pragma unroll
        for (int ma = 0; ma < 2; ma++) {
            #pragma unroll
            for (int h = 0; h < 2; h++) {
                int p = tile * 128 + wm * 32 + ma * 16 + h * 8 + gid;
                if (p >= NPOS) continue;
                float* op = op0 + (size_t)p * 256 + ntile * 128 + wn * 64 + tig * 2;
                #pragma unroll
                for (int na = 0; na < 8; na++) {
                    *(float2*)(op + na * 8) = make_float2(acc[ma][na][h * 2], acc[ma][na][h * 2 + 1]);
                }
            }
        }
    }
}

// ---------------- reduce pc partials (12-way) -> bias -> fp32 NCHW ----------------
__global__ void reducep_kernel(const float* __restrict__ part, const float* __restrict__ bias,
                               float* __restrict__ out) {
    int gid = blockIdx.x * 256 + threadIdx.x;   // over 7744*64 quads
    if (gid >= 7744 * 64) return;
    int p = gid >> 6, oc = (gid & 63) * 4;
    const size_t seg = (size_t)7744 * 256;
    const float* p0 = part + (size_t)p * 256 + oc;
    float4 v = *(const float4*)p0;
    #pragma unroll
    for (int k = 1; k < 12; k++) {
        float4 t = *(const float4*)(p0 + k * seg);
        v.x += t.x; v.y += t.y; v.z += t.z; v.w += t.w;
    }
    const float4 bv = *(const float4*)(bias + oc);
    v.x += bv.x; v.y += bv.y; v.z += bv.z; v.w += bv.w;
    int b = p / 484;
    int rem = p - b * 484;
    int rr = rem / 22, cx = rem - rr * 22;
    size_t base = (((size_t)b * 256 + oc) * 22 + rr) * 22 + cx;
    out[base]             = v.x;
    out[base + 484]       = v.y;
    out[base + 2 * 484]   = v.z;
    out[base + 3 * 484]   = v.w;
}

// ---------------- squash primary caps: p -> u ----------------
__global__ void squash_u_kernel() {
    int cap = blockIdx.x * 256 + threadIdx.x;
    if (cap >= BATCH * NI) return;
    const float4* pp = (const float4*)(g_p + (size_t)cap * 8);
    float4 a = pp[0], c = pp[1];
    float s2 = a.x * a.x + a.y * a.y + a.z * a.z + a.w * a.w
             + c.x * c.x + c.y * c.y + c.z * c.z + c.w * c.w;
    float f = s2 / (1.f + s2) * rsqrtf(s2 + EPSQ);
    a.x *= f; a.y *= f; a.z *= f; a.w *= f;
    c.x *= f; c.y *= f; c.z *= f; c.w *= f;
    float4* uo = (float4*)(g_u + (size_t)cap * 8);
    uo[0] = a; uo[1] = c;
}

// ---------------- u_hat (bf16 out) ----------------
__global__ __launch_bounds__(256)
void uhat_kernel(const float* __restrict__ W) {
    int gid = blockIdx.x * 256 + threadIdx.x;
    int d = gid & 15;
    int j = (gid >> 4) % 10;
    int i = gid / 160;
    if (i >= NI) return;
    const float4* Wp = (const float4*)(W + (((size_t)j * NI + i) * 16 + d) * 8);
    float4 w0 = Wp[0], w1 = Wp[1];
    for (int b = 0; b < BATCH; b++) {
        const float4* up = (const float4*)(g_u + ((size_t)b * NI + i) * 8);
        float4 u0 = up[0], u1 = up[1];
        float acc = w0.x * u0.x + w0.y * u0.y + w0.z * u0.z + w0.w * u0.w
                  + w1.x * u1.x + w1.y * u1.y + w1.z * u1.z + w1.w * u1.w;
        g_uhatb[(((size_t)b * NI + i) * 10 + j) * 16 + d] = __float2bfloat16(acc);
    }
}

// ---------------- routing: s[b,j,d] = sum_i softmax_j(u_hat*Vcum) * u_hat ----------------
__global__ __launch_bounds__(256)
void routing_s_kernel() {
    __shared__ float Vsh[160];
    __shared__ float ssh[160];
    int tid = threadIdx.x;
    int b = blockIdx.y;
    if (tid < 160) { Vsh[tid] = g_V[b * 160 + tid]; ssh[tid] = 0.f; }
    __syncthreads();
    int d = tid & 15, il = tid >> 4;
    float accj[10];
    #pragma unroll
    for (int j = 0; j < 10; j++) accj[j] = 0.f;

    const int per = NI / 32;
    int i0 = blockIdx.x * per;
    for (int i = i0 + il; i < i0 + per; i += 16) {
        const __nv_bfloat16* uh = g_uhatb + (((size_t)b * NI + i) * 10) * 16 + d;
        float uv[10], e[10];
        float m = -1e30f;
        #pragma unroll
        for (int j = 0; j < 10; j++) {
            uv[j] = __bfloat162float(uh[j * 16]);
            float l = uv[j] * Vsh[j * 16 + d];
            e[j] = l;
            m = fmaxf(m, l);
        }
        float se = 0.f;
        #pragma unroll
        for (int j = 0; j < 10; j++) { e[j] = __expf(e[j] - m); se += e[j]; }
        float inv = 1.f / se;
        #pragma unroll
        for (int j = 0; j < 10; j++) accj[j] += e[j] * inv * uv[j];
    }
    #pragma unroll
    for (int j = 0; j < 10; j++) atomicAdd(&ssh[j * 16 + d], accj[j]);
    __syncthreads();
    if (tid < 160) atomicAdd(&g_s[b * 160 + tid], ssh[tid]);
}

// ---------------- v update / final ----------------
__global__ void v_update_kernel(int last, float* __restrict__ dout) {
    __shared__ float s2sh[10];
    __shared__ float nrm[10];
    __shared__ int amax;
    int b = blockIdx.x, tid = threadIdx.x;
    int j = tid >> 4, d = tid & 15;
    if (tid < 10) s2sh[tid] = 0.f;
    __syncthreads();
    float sv = g_s[b * 160 + tid];
    atomicAdd(&s2sh[j], sv * sv);
    __syncthreads();
    float s2 = s2sh[j];
    float v = s2 / (1.f + s2) * sv * rsqrtf(s2 + EPSQ);
    if (!last) {
        g_V[b * 160 + tid] += v;
    } else {
        if (d == 0) nrm[j] = s2 / (1.f + s2) * sqrtf(s2) * rsqrtf(s2 + EPSQ);
        __syncthreads();
        if (tid == 0) {
            int bm = 0; float mx = nrm[0];
            for (int jj = 1; jj < 10; jj++)
                if (nrm[jj] > mx) { mx = nrm[jj]; bm = jj; }
            amax = bm;
        }
        if (d == 0) dout[b * 10 + j] = nrm[j];
        __syncthreads();
        g_masked[b * 160 + tid] = (j == amax) ? v : 0.f;
    }
}

// ---------------- decoder FC ----------------
__global__ void fc_kernel(const float* __restrict__ in, const float* __restrict__ W,
                          const float* __restrict__ bias, float* __restrict__ out,
                          int IN, int OUT, int act) {
    int gid = blockIdx.x * blockDim.x + threadIdx.x;
    if (gid >= BATCH * OUT) return;
    int o = gid % OUT, b = gid / OUT;
    const float* ip = in + (size_t)b * IN;
    float acc = bias[o];
    for (int k = 0; k < IN; k++) acc += ip[k] * W[(size_t)k * OUT + o];
    if (act == 1) acc = fmaxf(acc, 0.f);
    else          acc = 1.f / (1.f + __expf(-acc));
    out[gid] = acc;
}

// ---------------- launch ----------------
extern "C" void kernel_launch(void* const* d_in, const int* in_sizes, int n_in,
                              void* d_out, int out_size) {
    const float* x   = (const float*)d_in[0];
    const float* c1w = (const float*)d_in[1];
    const float* c1b = (const float*)d_in[2];
    const float* c2w = (const float*)d_in[3];
    const float* c2b = (const float*)d_in[4];
    const float* pcw = (const float*)d_in[5];
    const float* pcb = (const float*)d_in[6];
    const float* Wc  = (const float*)d_in[7];
    const float* w1  = (const float*)d_in[8];
    const float* b1  = (const float*)d_in[9];
    const float* w2  = (const float*)d_in[10];
    const float* b2  = (const float*)d_in[11];
    const float* w3  = (const float*)d_in[12];
    const float* b3  = (const float*)d_in[13];
    float* dout = (float*)d_out;

    __nv_bfloat16 *p_c1h, *p_c1l, *p_c2h, *p_c2l, *p_w2h, *p_w2l, *p_wph, *p_wpl;
    float *p_part, *p_p, *p_s, *p_V, *p_masked, *p_d1, *p_d2;
    cudaGetSymbolAddress((void**)&p_c1h, g_c1h);
    cudaGetSymbolAddress((void**)&p_c1l, g_c1l);
    cudaGetSymbolAddress((void**)&p_c2h, g_c2h);
    cudaGetSymbolAddress((void**)&p_c2l, g_c2l);
    cudaGetSymbolAddress((void**)&p_part, g_part);
    cudaGetSymbolAddress((void**)&p_p,  g_p);
    cudaGetSymbolAddress((void**)&p_w2h, g_w2h);
    cudaGetSymbolAddress((void**)&p_w2l, g_w2l);
    cudaGetSymbolAddress((void**)&p_wph, g_wph);
    cudaGetSymbolAddress((void**)&p_wpl, g_wpl);
    cudaGetSymbolAddress((void**)&p_s,  g_s);
    cudaGetSymbolAddress((void**)&p_V,  g_V);
    cudaGetSymbolAddress((void**)&p_masked, g_masked);
    cudaGetSymbolAddress((void**)&p_d1, g_d1);
    cudaGetSymbolAddress((void**)&p_d2, g_d2);

    // conv2: fused epilogue (bias+relu+bf16 split), no split-K
    auto conv2 = conv_mma_kernel<56, 56, 52, 52, 5, 1, 100, 1, 43264, true>;
    // pc: split-K 12, fp32 partials
    auto convp = conv_mma_kernel<52, 52, 22, 22, 9, 2, 324, 12, 7744, false>;
    cudaFuncSetAttribute(conv2, cudaFuncAttributeMaxDynamicSharedMemorySize, SMEM_CONV_TOTAL);
    cudaFuncSetAttribute(convp, cudaFuncAttributeMaxDynamicSharedMemorySize, SMEM_CONV_TOTAL);

    // weight split/swizzle transforms
    transform_wsplit_kernel<<<(100 * 8192 + 255) / 256, 256>>>(c2w, p_w2h, p_w2l, 5, 5, 100);
    transform_wsplit_kernel<<<(324 * 8192 + 255) / 256, 256>>>(pcw, p_wph, p_wpl, 9, 9, 324);

    // conv1 (NHWC bf16 hi/lo out)
    conv1_kernel<<<dim3(4, 8, 16), 196>>>(x, c1w, c1b, p_c1h, p_c1l);

    // conv2: direct bf16 hi/lo NHWC output
    conv2<<<dim3(338, 2, 1), 256, SMEM_CONV_TOTAL>>>(p_c1h, p_c1l, p_w2h, p_w2l, c2b,
                                                     p_c2h, p_c2l, nullptr);

    // pc: split-K=12 partials, then reduce (bias -> fp32 NCHW)
    convp<<<dim3(61, 2, 12), 256, SMEM_CONV_TOTAL>>>(p_c2h, p_c2l, p_wph, p_wpl, nullptr,
                                                     nullptr, nullptr, p_part);
    reducep_kernel<<<(7744 * 64 + 255) / 256, 256>>>(p_part, pcb, p_p);

    squash_u_kernel<<<(BATCH * NI + 255) / 256, 256>>>();
    uhat_kernel<<<((size_t)NI * 160 + 255) / 256, 256>>>(Wc);

    cudaMemsetAsync(p_V, 0, BATCH * 160 * sizeof(float));
    for (int r = 0; r < 3; r++) {
        cudaMemsetAsync(p_s, 0, BATCH * 160 * sizeof(float));
        routing_s_kernel<<<dim3(32, 16), 256>>>();
        v_update_kernel<<<16, 160>>>(r == 2 ? 1 : 0, dout);
    }

    fc_kernel<<<(BATCH * 512 + 255) / 256, 256>>>(p_masked, w1, b1, p_d1, 160, 512, 1);
    fc_kernel<<<(BATCH * 1024 + 255) / 256, 256>>>(p_d1, w2, b2, p_d2, 512, 1024, 1);
    fc_kernel<<<(BATCH * 4096 + 255) / 256, 256>>>(p_d2, w3, b3, dout + 160, 1024, 4096, 2);
}

// round 8
// speedup vs baseline: 3.7645x; 1.0920x over previous
#include <cuda_runtime.h>
#include <cuda_bf16.h>
#include <cstdint>

#define EPSQ 1e-8f

static const int BATCH = 16;
static const int NI = 15488;

// ---------------- scratch (device globals) ----------------
__device__ __nv_bfloat16 g_c1h[(size_t)16 * 56 * 56 * 256];   // NHWC hi
__device__ __nv_bfloat16 g_c1l[(size_t)16 * 56 * 56 * 256];   // NHWC lo
__device__ __nv_bfloat16 g_c2h[(size_t)16 * 52 * 52 * 256];
__device__ __nv_bfloat16 g_c2l[(size_t)16 * 52 * 52 * 256];
__device__ float g_part[(size_t)12 * 7744 * 256];             // split-K partials (max user: pc 95MB; conv2 uses 88MB)
__device__ float g_p [(size_t)16 * 256 * 22 * 22];            // NCHW
__device__ float g_u [(size_t)16 * 15488 * 8];
__device__ __nv_bfloat16 g_uhatb[(size_t)16 * 15488 * 10 * 16];
__device__ __nv_bfloat16 g_w2h[(size_t)100 * 16384];          // [chunk][64k x 256n swizzled]
__device__ __nv_bfloat16 g_w2l[(size_t)100 * 16384];
__device__ __nv_bfloat16 g_wph[(size_t)324 * 16384];
__device__ __nv_bfloat16 g_wpl[(size_t)324 * 16384];
__device__ float g_s[16 * 160];
__device__ float g_V[16 * 160];
__device__ float g_masked[16 * 160];
__device__ float g_d1[16 * 512];
__device__ float g_d2[16 * 1024];

// ---------------- PTX helpers (base-ISA, compiles for compute_103) ----------------
__device__ __forceinline__ uint32_t smem_to_u32(const void* p) {
    uint32_t a;
    asm("{ .reg .u64 t; cvta.to.shared.u64 t, %1; cvt.u32.u64 %0, t; }" : "=r"(a) : "l"(p));
    return a;
}
__device__ __forceinline__ void ldsm_x4(uint32_t& r0, uint32_t& r1, uint32_t& r2, uint32_t& r3, uint32_t addr) {
    asm volatile("ldmatrix.sync.aligned.m8n8.x4.shared.b16 {%0,%1,%2,%3}, [%4];"
                 : "=r"(r0), "=r"(r1), "=r"(r2), "=r"(r3) : "r"(addr));
}
__device__ __forceinline__ void ldsm_x4_t(uint32_t& r0, uint32_t& r1, uint32_t& r2, uint32_t& r3, uint32_t addr) {
    asm volatile("ldmatrix.sync.aligned.m8n8.x4.trans.shared.b16 {%0,%1,%2,%3}, [%4];"
                 : "=r"(r0), "=r"(r1), "=r"(r2), "=r"(r3) : "r"(addr));
}
__device__ __forceinline__ void mma16816(float* c, const uint32_t* a, const uint32_t* b) {
    asm volatile("mma.sync.aligned.m16n8k16.row.col.f32.bf16.bf16.f32 "
                 "{%0,%1,%2,%3}, {%4,%5,%6,%7}, {%8,%9}, {%0,%1,%2,%3};"
                 : "+f"(c[0]), "+f"(c[1]), "+f"(c[2]), "+f"(c[3])
                 : "r"(a[0]), "r"(a[1]), "r"(a[2]), "r"(a[3]), "r"(b[0]), "r"(b[1]));
}
#define CP_ASYNC16(dst, src, sz) \
    asm volatile("cp.async.cg.shared.global [%0], [%1], 16, %2;" :: "r"(dst), "l"(src), "r"(sz))
#define CP_COMMIT() asm volatile("cp.async.commit_group;" ::: "memory")
#define CP_WAIT(n)  asm volatile("cp.async.wait_group %0;" :: "n"(n) : "memory")

// ---------------- weight split+swizzle transform ----------------
// image: [chunk][64 rows(k=ic) x 256 cols(n=oc) bf16, swizzled (512B rows, XOR (k&7)<<4)]
__global__ void transform_wsplit_kernel(const float* __restrict__ w,
                                        __nv_bfloat16* __restrict__ wh,
                                        __nv_bfloat16* __restrict__ wl,
                                        int KH, int KW, int NCHUNK) {
    int idx = blockIdx.x * 256 + threadIdx.x;    // n-pair index
    int total = NCHUNK * 64 * 128;
    if (idx >= total) return;
    int np = idx & 127;            // n = np*2
    int k  = (idx >> 7) & 63;      // ic within chunk
    int chunk = idx >> 13;
    int kyx = chunk >> 2;
    int ic = (chunk & 3) * 64 + k;
    int ky = kyx / KW, kx = kyx % KW;
    int oc = np * 2;
    size_t KHW = (size_t)KH * KW;
    size_t wi = (((size_t)oc * 256 + ic) * KH + ky) * KW + kx;
    float f0 = w[wi];
    float f1 = w[wi + 256 * KHW];
    __nv_bfloat16 h0 = __float2bfloat16(f0);
    __nv_bfloat16 h1 = __float2bfloat16(f1);
    __nv_bfloat16 l0 = __float2bfloat16(f0 - __bfloat162float(h0));
    __nv_bfloat16 l1 = __float2bfloat16(f1 - __bfloat162float(h1));
    uint32_t hp = ((uint32_t)__bfloat16_as_ushort(h1) << 16) | __bfloat16_as_ushort(h0);
    uint32_t lp = ((uint32_t)__bfloat16_as_ushort(l1) << 16) | __bfloat16_as_ushort(l0);
    int off = k * 512 + np * 4;
    int sw = off ^ ((k & 7) << 4);
    size_t tb = (size_t)chunk * 32768;
    *(uint32_t*)((char*)wh + tb + sw) = hp;
    *(uint32_t*)((char*)wl + tb + sw) = lp;
}

// ---------------- conv1: 1->256, 9x9, s1, 64->56, NHWC bf16 hi/lo out ----------------
// 28x28 output tile per CTA; thread = 4 positions x 4 oc register tile.
__global__ __launch_bounds__(196)
void conv1_kernel(const float* __restrict__ x, const float* __restrict__ w,
                  const float* __restrict__ bias,
                  __nv_bfloat16* __restrict__ oh, __nv_bfloat16* __restrict__ ol) {
    __shared__ float s_in[36 * 36];
    __shared__ float s_w[4 * 81];
    int tid = threadIdx.x;
    int tileY = blockIdx.x >> 1, tileX = blockIdx.x & 1;
    int b = blockIdx.z;
    int ocg = blockIdx.y;

    for (int idx = tid; idx < 1296; idx += 196) {
        int r = idx / 36, cc = idx % 36;
        s_in[idx] = x[((size_t)b * 64 + tileY * 28 + r) * 64 + tileX * 28 + cc];
    }
    int sy = tid / 14, sx = tid % 14;

    for (int oi = 0; oi < 32; oi += 4) {
        __syncthreads();
        for (int idx = tid; idx < 4 * 81; idx += 196) {
            int o = idx / 81, k = idx % 81;
            s_w[idx] = w[(size_t)(ocg * 32 + oi + o) * 81 + k];
        }
        __syncthreads();
        float acc[2][2][4];
        #pragma unroll
        for (int a = 0; a < 2; a++)
            #pragma unroll
            for (int q = 0; q < 2; q++)
                #pragma unroll
                for (int o = 0; o < 4; o++) acc[a][q][o] = 0.f;
        for (int ky = 0; ky < 9; ky++) {
            #pragma unroll
            for (int kx = 0; kx < 9; kx++) {
                int k = ky * 9 + kx;
                float w0 = s_w[k], w1 = s_w[81 + k], w2 = s_w[162 + k], w3 = s_w[243 + k];
                #pragma unroll
                for (int a = 0; a < 2; a++) {
                    #pragma unroll
                    for (int q = 0; q < 2; q++) {
                        float v = s_in[(sy + 14 * a + ky) * 36 + sx + 14 * q + kx];
                        acc[a][q][0] += v * w0;
                        acc[a][q][1] += v * w1;
                        acc[a][q][2] += v * w2;
                        acc[a][q][3] += v * w3;
                    }
                }
            }
        }
        int oc = ocg * 32 + oi;
        float b0 = bias[oc], b1 = bias[oc + 1], b2 = bias[oc + 2], b3 = bias[oc + 3];
        #pragma unroll
        for (int a = 0; a < 2; a++) {
            #pragma unroll
            for (int q = 0; q < 2; q++) {
                int oy = tileY * 28 + a * 14 + sy;
                int ox = tileX * 28 + q * 14 + sx;
                size_t ob = ((size_t)(b * 56 + oy) * 56 + ox) * 256 + oc;
                float v[4];
                v[0] = fmaxf(acc[a][q][0] + b0, 0.f);
                v[1] = fmaxf(acc[a][q][1] + b1, 0.f);
                v[2] = fmaxf(acc[a][q][2] + b2, 0.f);
                v[3] = fmaxf(acc[a][q][3] + b3, 0.f);
                ushort hh[4], ll[4];
                #pragma unroll
                for (int o = 0; o < 4; o++) {
                    __nv_bfloat16 h = __float2bfloat16(v[o]);
                    __nv_bfloat16 l = __float2bfloat16(v[o] - __bfloat162float(h));
                    hh[o] = __bfloat16_as_ushort(h);
                    ll[o] = __bfloat16_as_ushort(l);
                }
                *(uint2*)(oh + ob) = make_uint2(((uint32_t)hh[1] << 16) | hh[0],
                                                ((uint32_t)hh[3] << 16) | hh[2]);
                *(uint2*)(ol + ob) = make_uint2(((uint32_t)ll[1] << 16) | ll[0],
                                                ((uint32_t)ll[3] << 16) | ll[2]);
            }
        }
    }
}

// ---------------- HMMA implicit-GEMM conv, 2-stage cp.async, ONE sync per chunk ----------------
// Block: 512 thr (16 warps, 4Mx4N); tile M=128 pos x N=256 oc; warp tile 32x64.
// SMEM stage (96KB): Ah 16K | Al 16K | Bh 32K | Bl 32K. 2 stages.
#define STG_STRIDE 98304
#define SMEM_CONV_TOTAL (2 * STG_STRIDE)

template<int IH, int IW, int OH, int OW, int KW, int STRIDE, int NCHUNK, int KSPLIT, int NPOS>
__global__ __launch_bounds__(512, 1)
void conv_mma_kernel(const __nv_bfloat16* __restrict__ inh,
                     const __nv_bfloat16* __restrict__ inl,
                     const __nv_bfloat16* __restrict__ wh,
                     const __nv_bfloat16* __restrict__ wl,
                     float* __restrict__ part) {
    extern __shared__ char smem[];
    const uint32_t sb = smem_to_u32(smem);
    const int tid = threadIdx.x;
    const int wid = tid >> 5, lid = tid & 31;
    const int tile = blockIdx.x;

    // A fill identity: row r = tid>>2 (0..127), sp = tid&3 (2 x 16B segs each)
    const int r = tid >> 2, sp = tid & 3;
    const int p_mine = tile * 128 + r;
    const bool pvalid = p_mine < NPOS;
    int pb = 0, pr = 0, pcx = 0;
    if (pvalid) {
        pb = p_mine / (OH * OW);
        int rem = p_mine - pb * (OH * OW);
        pr = rem / OW;
        pcx = rem - pr * OW;
    }
    const int asz = pvalid ? 16 : 0;

    const int wm = wid >> 2, wn = wid & 3;
    const int lane15 = lid & 15, lane16 = lid >> 4;
    const int gid = lid >> 2, tig = lid & 3;

    float acc[2][8][4];
    #pragma unroll
    for (int ma = 0; ma < 2; ma++)
        #pragma unroll
        for (int na = 0; na < 8; na++)
            #pragma unroll
            for (int q = 0; q < 4; q++) acc[ma][na][q] = 0.f;

    const int NC = NCHUNK / KSPLIT;
    const int coff = blockIdx.y * NC;

    auto fill = [&](int stage, int chunk) {
        uint32_t s0 = sb + stage * STG_STRIDE;
        // B: straight copy of pre-swizzled 32KB hi + 32KB lo
        const char* bh = (const char*)(wh + (size_t)chunk * 16384);
        const char* bl = (const char*)(wl + (size_t)chunk * 16384);
        #pragma unroll
        for (int i = 0; i < 4; i++) {
            uint32_t u = (tid + i * 512) * 16;
            CP_ASYNC16(s0 + 32768 + u, bh + u, 16);
            CP_ASYNC16(s0 + 65536 + u, bl + u, 16);
        }
        // A: gather NHWC bf16 rows (64 ch = 128B hi + 128B lo)
        const int kyx = chunk >> 2;
        const int ic0 = (chunk & 3) * 64;
        const int ky = kyx / KW, kx = kyx % KW;
        size_t srcbase = 0;
        if (pvalid) {
            int iy = pr * STRIDE + ky, ix = pcx * STRIDE + kx;
            srcbase = (((size_t)pb * IH + iy) * IW + ix) * 256 + ic0;
        }
        #pragma unroll
        for (int q = 0; q < 2; q++) {
            int seg = sp * 2 + q;
            uint32_t off = r * 128 + seg * 16;
            uint32_t sw = off ^ ((r & 7) << 4);
            CP_ASYNC16(s0 + sw,         (const char*)(inh + srcbase + seg * 8), asz);
            CP_ASYNC16(s0 + 16384 + sw, (const char*)(inl + srcbase + seg * 8), asz);
        }
    };

    fill(0, coff);
    CP_COMMIT();

    for (int i = 0; i < NC; ++i) {
        CP_WAIT(0);            // fill(i) complete (fill(i+1) not yet issued)
        __syncthreads();       // also guards stage (i+1)&1 reads from compute(i-1)
        if (i + 1 < NC) {      // prefetch next chunk; lands during compute(i)
            fill((i + 1) & 1, coff + i + 1);
            CP_COMMIT();
        }

        const uint32_t s0 = sb + (i & 1) * STG_STRIDE;
        #pragma unroll
        for (int ks = 0; ks < 4; ks++) {
            uint32_t Bh[8][2], Bl[8][2];
            const int brow = ks * 16 + lane15;
            #pragma unroll
            for (int q = 0; q < 4; q++) {
                uint32_t off = brow * 512 + wn * 128 + q * 32 + lane16 * 16;
                uint32_t sw = off ^ ((brow & 7) << 4);
                ldsm_x4_t(Bh[2*q][0], Bh[2*q][1], Bh[2*q+1][0], Bh[2*q+1][1], s0 + 32768 + sw);
                ldsm_x4_t(Bl[2*q][0], Bl[2*q][1], Bl[2*q+1][0], Bl[2*q+1][1], s0 + 65536 + sw);
            }
            #pragma unroll
            for (int ma = 0; ma < 2; ma++) {
                const int arow = wm * 32 + ma * 16 + lane15;
                uint32_t offA = arow * 128 + ks * 32 + lane16 * 16;
                uint32_t swA = offA ^ ((arow & 7) << 4);
                uint32_t a[4];
                ldsm_x4(a[0], a[1], a[2], a[3], s0 + swA);
                #pragma unroll
                for (int na = 0; na < 8; na++) mma16816(acc[ma][na], a, Bh[na]);
                #pragma unroll
                for (int na = 0; na < 8; na++) mma16816(acc[ma][na], a, Bl[na]);
                ldsm_x4(a[0], a[1], a[2], a[3], s0 + 16384 + swA);
                #pragma unroll
                for (int na = 0; na < 8; na++) mma16816(acc[ma][na], a, Bh[na]);
            }
        }
    }

    // ---- epilogue: fp32 partial store ----
    float* op0 = part + (size_t)blockIdx.y * NPOS * 256;
    #pragma unroll
    for (int ma = 0; ma < 2; ma++) {
        #pragma unroll
        for (int h = 0; h < 2; h++) {
            int p = tile * 128 + wm * 32 + ma * 16 + h * 8 + gid;
            if (p >= NPOS) continue;
            float* op = op0 + (size_t)p * 256 + wn * 64 + tig * 2;
            #pragma unroll
            for (int na = 0; na < 8; na++) {
                *(float2*)(op + na * 8) = make_float2(acc[ma][na][h * 2], acc[ma][na][h * 2 + 1]);
            }
        }
    }
}

// ---------------- reduce conv2 partials (2-way) -> bias+relu -> bf16 hi/lo NHWC ----------------
__global__ void reduce2_kernel(const float* __restrict__ part, const float* __restrict__ bias,
                               __nv_bfloat16* __restrict__ oh, __nv_bfloat16* __restrict__ ol) {
    size_t gid = (size_t)blockIdx.x * 256 + threadIdx.x;   // over 43264*128 pairs
    if (gid >= (size_t)43264 * 128) return;
    int p = (int)(gid >> 7);
    int oc = ((int)gid & 127) * 2;
    const float* p0 = part + (size_t)p * 256 + oc;
    const size_t half = (size_t)43264 * 256;
    float v0 = fmaxf(p0[0] + p0[half]     + bias[oc],     0.f);
    float v1 = fmaxf(p0[1] + p0[half + 1] + bias[oc + 1], 0.f);
    __nv_bfloat16 h0 = __float2bfloat16(v0);
    __nv_bfloat16 h1 = __float2bfloat16(v1);
    __nv_bfloat16 l0 = __float2bfloat16(v0 - __bfloat162float(h0));
    __nv_bfloat16 l1 = __float2bfloat16(v1 - __bfloat162float(h1));
    size_t o = (size_t)p * 256 + oc;
    *(uint32_t*)(oh + o) = ((uint32_t)__bfloat16_as_ushort(h1) << 16) | __bfloat16_as_ushort(h0);
    *(uint32_t*)(ol + o) = ((uint32_t)__bfloat16_as_ushort(l1) << 16) | __bfloat16_as_ushort(l0);
}

// ---------------- reduce pc partials (12-way) -> bias -> fp32 NCHW ----------------
__global__ void reducep_kernel(const float* __restrict__ part, const float* __restrict__ bias,
                               float* __restrict__ out) {
    int gid = blockIdx.x * 256 + threadIdx.x;   // over 7744*64 quads
    if (gid >= 7744 * 64) return;
    int p = gid >> 6, oc = (gid & 63) * 4;
    const size_t seg = (size_t)7744 * 256;
    const float* p0 = part + (size_t)p * 256 + oc;
    float4 v = *(const float4*)p0;
    #pragma unroll
    for (int k = 1; k < 12; k++) {
        float4 t = *(const float4*)(p0 + k * seg);
        v.x += t.x; v.y += t.y; v.z += t.z; v.w += t.w;
    }
    const float4 bv = *(const float4*)(bias + oc);
    v.x += bv.x; v.y += bv.y; v.z += bv.z; v.w += bv.w;
    int b = p / 484;
    int rem = p - b * 484;
    int rr = rem / 22, cx = rem - rr * 22;
    size_t base = (((size_t)b * 256 + oc) * 22 + rr) * 22 + cx;
    out[base]             = v.x;
    out[base + 484]       = v.y;
    out[base + 2 * 484]   = v.z;
    out[base + 3 * 484]   = v.w;
}

// ---------------- squash primary caps: p -> u ----------------
__global__ void squash_u_kernel() {
    int cap = blockIdx.x * 256 + threadIdx.x;
    if (cap >= BATCH * NI) return;
    const float4* pp = (const float4*)(g_p + (size_t)cap * 8);
    float4 a = pp[0], c = pp[1];
    float s2 = a.x * a.x + a.y * a.y + a.z * a.z + a.w * a.w
             + c.x * c.x + c.y * c.y + c.z * c.z + c.w * c.w;
    float f = s2 / (1.f + s2) * rsqrtf(s2 + EPSQ);
    a.x *= f; a.y *= f; a.z *= f; a.w *= f;
    c.x *= f; c.y *= f; c.z *= f; c.w *= f;
    float4* uo = (float4*)(g_u + (size_t)cap * 8);
    uo[0] = a; uo[1] = c;
}

// ---------------- u_hat (bf16 out) ----------------
__global__ __launch_bounds__(256)
void uhat_kernel(const float* __restrict__ W) {
    int gid = blockIdx.x * 256 + threadIdx.x;
    int d = gid & 15;
    int j = (gid >> 4) % 10;
    int i = gid / 160;
    if (i >= NI) return;
    const float4* Wp = (const float4*)(W + (((size_t)j * NI + i) * 16 + d) * 8);
    float4 w0 = Wp[0], w1 = Wp[1];
    for (int b = 0; b < BATCH; b++) {
        const float4* up = (const float4*)(g_u + ((size_t)b * NI + i) * 8);
        float4 u0 = up[0], u1 = up[1];
        float acc = w0.x * u0.x + w0.y * u0.y + w0.z * u0.z + w0.w * u0.w
                  + w1.x * u1.x + w1.y * u1.y + w1.z * u1.z + w1.w * u1.w;
        g_uhatb[(((size_t)b * NI + i) * 10 + j) * 16 + d] = __float2bfloat16(acc);
    }
}

// ---------------- routing: s[b,j,d] = sum_i softmax_j(u_hat*Vcum) * u_hat ----------------
__global__ __launch_bounds__(256)
void routing_s_kernel() {
    __shared__ float Vsh[160];
    __shared__ float ssh[160];
    int tid = threadIdx.x;
    int b = blockIdx.y;
    if (tid < 160) { Vsh[tid] = g_V[b * 160 + tid]; ssh[tid] = 0.f; }
    __syncthreads();
    int d = tid & 15, il = tid >> 4;
    float accj[10];
    #pragma unroll
    for (int j = 0; j < 10; j++) accj[j] = 0.f;

    const int per = NI / 32;
    int i0 = blockIdx.x * per;
    for (int i = i0 + il; i < i0 + per; i += 16) {
        const __nv_bfloat16* uh = g_uhatb + (((size_t)b * NI + i) * 10) * 16 + d;
        float uv[10], e[10];
        float m = -1e30f;
        #pragma unroll
        for (int j = 0; j < 10; j++) {
            uv[j] = __bfloat162float(uh[j * 16]);
            float l = uv[j] * Vsh[j * 16 + d];
            e[j] = l;
            m = fmaxf(m, l);
        }
        float se = 0.f;
        #pragma unroll
        for (int j = 0; j < 10; j++) { e[j] = __expf(e[j] - m); se += e[j]; }
        float inv = 1.f / se;
        #pragma unroll
        for (int j = 0; j < 10; j++) accj[j] += e[j] * inv * uv[j];
    }
    #pragma unroll
    for (int j = 0; j < 10; j++) atomicAdd(&ssh[j * 16 + d], accj[j]);
    __syncthreads();
    if (tid < 160) atomicAdd(&g_s[b * 160 + tid], ssh[tid]);
}

// ---------------- v update / final ----------------
__global__ void v_update_kernel(int last, float* __restrict__ dout) {
    __shared__ float s2sh[10];
    __shared__ float nrm[10];
    __shared__ int amax;
    int b = blockIdx.x, tid = threadIdx.x;
    int j = tid >> 4, d = tid & 15;
    if (tid < 10) s2sh[tid] = 0.f;
    __syncthreads();
    float sv = g_s[b * 160 + tid];
    atomicAdd(&s2sh[j], sv * sv);
    __syncthreads();
    float s2 = s2sh[j];
    float v = s2 / (1.f + s2) * sv * rsqrtf(s2 + EPSQ);
    if (!last) {
        g_V[b * 160 + tid] += v;
    } else {
        if (d == 0) nrm[j] = s2 / (1.f + s2) * sqrtf(s2) * rsqrtf(s2 + EPSQ);
        __syncthreads();
        if (tid == 0) {
            int bm = 0; float mx = nrm[0];
            for (int jj = 1; jj < 10; jj++)
                if (nrm[jj] > mx) { mx = nrm[jj]; bm = jj; }
            amax = bm;
        }
        if (d == 0) dout[b * 10 + j] = nrm[j];
        __syncthreads();
        g_masked[b * 160 + tid] = (j == amax) ? v : 0.f;
    }
}

// ---------------- decoder FC ----------------
__global__ void fc_kernel(const float* __restrict__ in, const float* __restrict__ W,
                          const float* __restrict__ bias, float* __restrict__ out,
                          int IN, int OUT, int act) {
    int gid = blockIdx.x * blockDim.x + threadIdx.x;
    if (gid >= BATCH * OUT) return;
    int o = gid % OUT, b = gid / OUT;
    const float* ip = in + (size_t)b * IN;
    float acc = bias[o];
    for (int k = 0; k < IN; k++) acc += ip[k] * W[(size_t)k * OUT + o];
    if (act == 1) acc = fmaxf(acc, 0.f);
    else          acc = 1.f / (1.f + __expf(-acc));
    out[gid] = acc;
}

// ---------------- launch ----------------
extern "C" void kernel_launch(void* const* d_in, const int* in_sizes, int n_in,
                              void* d_out, int out_size) {
    const float* x   = (const float*)d_in[0];
    const float* c1w = (const float*)d_in[1];
    const float* c1b = (const float*)d_in[2];
    const float* c2w = (const float*)d_in[3];
    const float* c2b = (const float*)d_in[4];
    const float* pcw = (const float*)d_in[5];
    const float* pcb = (const float*)d_in[6];
    const float* Wc  = (const float*)d_in[7];
    const float* w1  = (const float*)d_in[8];
    const float* b1  = (const float*)d_in[9];
    const float* w2  = (const float*)d_in[10];
    const float* b2  = (const float*)d_in[11];
    const float* w3  = (const float*)d_in[12];
    const float* b3  = (const float*)d_in[13];
    float* dout = (float*)d_out;

    __nv_bfloat16 *p_c1h, *p_c1l, *p_c2h, *p_c2l, *p_w2h, *p_w2l, *p_wph, *p_wpl;
    float *p_part, *p_p, *p_s, *p_V, *p_masked, *p_d1, *p_d2;
    cudaGetSymbolAddress((void**)&p_c1h, g_c1h);
    cudaGetSymbolAddress((void**)&p_c1l, g_c1l);
    cudaGetSymbolAddress((void**)&p_c2h, g_c2h);
    cudaGetSymbolAddress((void**)&p_c2l, g_c2l);
    cudaGetSymbolAddress((void**)&p_part, g_part);
    cudaGetSymbolAddress((void**)&p_p,  g_p);
    cudaGetSymbolAddress((void**)&p_w2h, g_w2h);
    cudaGetSymbolAddress((void**)&p_w2l, g_w2l);
    cudaGetSymbolAddress((void**)&p_wph, g_wph);
    cudaGetSymbolAddress((void**)&p_wpl, g_wpl);
    cudaGetSymbolAddress((void**)&p_s,  g_s);
    cudaGetSymbolAddress((void**)&p_V,  g_V);
    cudaGetSymbolAddress((void**)&p_masked, g_masked);
    cudaGetSymbolAddress((void**)&p_d1, g_d1);
    cudaGetSymbolAddress((void**)&p_d2, g_d2);

    // conv2: IH=56 OH=52 KW=5 S=1 NCHUNK=100 KSPLIT=2 NPOS=43264
    auto conv2 = conv_mma_kernel<56, 56, 52, 52, 5, 1, 100, 2, 43264>;
    // pc: IH=52 OH=22 KW=9 S=2 NCHUNK=324 KSPLIT=12 NPOS=7744
    auto convp = conv_mma_kernel<52, 52, 22, 22, 9, 2, 324, 12, 7744>;
    cudaFuncSetAttribute(conv2, cudaFuncAttributeMaxDynamicSharedMemorySize, SMEM_CONV_TOTAL);
    cudaFuncSetAttribute(convp, cudaFuncAttributeMaxDynamicSharedMemorySize, SMEM_CONV_TOTAL);

    // weight split/swizzle transforms
    transform_wsplit_kernel<<<(100 * 64 * 128 + 255) / 256, 256>>>(c2w, p_w2h, p_w2l, 5, 5, 100);
    transform_wsplit_kernel<<<(324 * 64 * 128 + 255) / 256, 256>>>(pcw, p_wph, p_wpl, 9, 9, 324);

    // conv1 (NHWC bf16 hi/lo out)
    conv1_kernel<<<dim3(4, 8, 16), 196>>>(x, c1w, c1b, p_c1h, p_c1l);

    // conv2: split-K=2 partials, then reduce (bias+relu -> bf16 hi/lo)
    conv2<<<dim3(338, 2), 512, SMEM_CONV_TOTAL>>>(p_c1h, p_c1l, p_w2h, p_w2l, p_part);
    reduce2_kernel<<<(int)(((size_t)43264 * 128 + 255) / 256), 256>>>(p_part, c2b, p_c2h, p_c2l);

    // pc: split-K=12 partials, then reduce (bias -> fp32 NCHW)
    convp<<<dim3(61, 12), 512, SMEM_CONV_TOTAL>>>(p_c2h, p_c2l, p_wph, p_wpl, p_part);
    reducep_kernel<<<(7744 * 64 + 255) / 256, 256>>>(p_part, pcb, p_p);

    squash_u_kernel<<<(BATCH * NI + 255) / 256, 256>>>();
    uhat_kernel<<<((size_t)NI * 160 + 255) / 256, 256>>>(Wc);

    cudaMemsetAsync(p_V, 0, BATCH * 160 * sizeof(float));
    for (int r = 0; r < 3; r++) {
        cudaMemsetAsync(p_s, 0, BATCH * 160 * sizeof(float));
        routing_s_kernel<<<dim3(32, 16), 256>>>();
        v_update_kernel<<<16, 160>>>(r == 2 ? 1 : 0, dout);
    }

    fc_kernel<<<(BATCH * 512 + 255) / 256, 256>>>(p_masked, w1, b1, p_d1, 160, 512, 1);
    fc_kernel<<<(BATCH * 1024 + 255) / 256, 256>>>(p_d1, w2, b2, p_d2, 512, 1024, 1);
    fc_kernel<<<(BATCH * 4096 + 255) / 256, 256>>>(p_d2, w3, b3, dout + 160, 1024, 4096, 2);
}

// round 9
// speedup vs baseline: 3.7740x; 1.0025x over previous
#include <cuda_runtime.h>
#include <cuda_bf16.h>
#include <cstdint>

#define EPSQ 1e-8f

static const int BATCH = 16;
static const int NI = 15488;

// ---------------- scratch (device globals) ----------------
__device__ __nv_bfloat16 g_c1h[(size_t)16 * 56 * 56 * 256];   // NHWC hi
__device__ __nv_bfloat16 g_c1l[(size_t)16 * 56 * 56 * 256];   // NHWC lo
__device__ __nv_bfloat16 g_c2h[(size_t)16 * 52 * 52 * 256];
__device__ __nv_bfloat16 g_c2l[(size_t)16 * 52 * 52 * 256];
__device__ float g_part[(size_t)12 * 7744 * 256];             // split-K partials (max user: pc 95MB; conv2 uses 88MB)
__device__ float g_p [(size_t)16 * 256 * 22 * 22];            // NCHW
__device__ float g_u [(size_t)16 * 15488 * 8];
__device__ __nv_bfloat16 g_uhatb[(size_t)16 * 15488 * 10 * 16];
__device__ __nv_bfloat16 g_w2h[(size_t)100 * 16384];          // [chunk][64k x 256n swizzled]
__device__ __nv_bfloat16 g_w2l[(size_t)100 * 16384];
__device__ __nv_bfloat16 g_wph[(size_t)324 * 16384];
__device__ __nv_bfloat16 g_wpl[(size_t)324 * 16384];
__device__ float g_s[16 * 160];
__device__ float g_V[16 * 160];
__device__ float g_masked[16 * 160];
__device__ float g_d1[16 * 512];
__device__ float g_d2[16 * 1024];

// ---------------- PTX helpers (base-ISA, compiles for compute_103) ----------------
__device__ __forceinline__ uint32_t smem_to_u32(const void* p) {
    uint32_t a;
    asm("{ .reg .u64 t; cvta.to.shared.u64 t, %1; cvt.u32.u64 %0, t; }" : "=r"(a) : "l"(p));
    return a;
}
__device__ __forceinline__ void ldsm_x4(uint32_t& r0, uint32_t& r1, uint32_t& r2, uint32_t& r3, uint32_t addr) {
    asm volatile("ldmatrix.sync.aligned.m8n8.x4.shared.b16 {%0,%1,%2,%3}, [%4];"
                 : "=r"(r0), "=r"(r1), "=r"(r2), "=r"(r3) : "r"(addr));
}
__device__ __forceinline__ void ldsm_x4_t(uint32_t& r0, uint32_t& r1, uint32_t& r2, uint32_t& r3, uint32_t addr) {
    asm volatile("ldmatrix.sync.aligned.m8n8.x4.trans.shared.b16 {%0,%1,%2,%3}, [%4];"
                 : "=r"(r0), "=r"(r1), "=r"(r2), "=r"(r3) : "r"(addr));
}
__device__ __forceinline__ void mma16816(float* c, const uint32_t* a, const uint32_t* b) {
    asm volatile("mma.sync.aligned.m16n8k16.row.col.f32.bf16.bf16.f32 "
                 "{%0,%1,%2,%3}, {%4,%5,%6,%7}, {%8,%9}, {%0,%1,%2,%3};"
                 : "+f"(c[0]), "+f"(c[1]), "+f"(c[2]), "+f"(c[3])
                 : "r"(a[0]), "r"(a[1]), "r"(a[2]), "r"(a[3]), "r"(b[0]), "r"(b[1]));
}
#define CP_ASYNC16(dst, src, sz) \
    asm volatile("cp.async.cg.shared.global [%0], [%1], 16, %2;" :: "r"(dst), "l"(src), "r"(sz))
#define CP_COMMIT() asm volatile("cp.async.commit_group;" ::: "memory")
#define CP_WAIT(n)  asm volatile("cp.async.wait_group %0;" :: "n"(n) : "memory")

// ---------------- weight split+swizzle transform ----------------
// image: [chunk][64 rows(k=ic) x 256 cols(n=oc) bf16, swizzled (512B rows, XOR (k&7)<<4)]
__global__ void transform_wsplit_kernel(const float* __restrict__ w,
                                        __nv_bfloat16* __restrict__ wh,
                                        __nv_bfloat16* __restrict__ wl,
                                        int KH, int KW, int NCHUNK) {
    int idx = blockIdx.x * 256 + threadIdx.x;    // n-pair index
    int total = NCHUNK * 64 * 128;
    if (idx >= total) return;
    int np = idx & 127;            // n = np*2
    int k  = (idx >> 7) & 63;      // ic within chunk
    int chunk = idx >> 13;
    int kyx = chunk >> 2;
    int ic = (chunk & 3) * 64 + k;
    int ky = kyx / KW, kx = kyx % KW;
    int oc = np * 2;
    size_t KHW = (size_t)KH * KW;
    size_t wi = (((size_t)oc * 256 + ic) * KH + ky) * KW + kx;
    float f0 = w[wi];
    float f1 = w[wi + 256 * KHW];
    __nv_bfloat16 h0 = __float2bfloat16(f0);
    __nv_bfloat16 h1 = __float2bfloat16(f1);
    __nv_bfloat16 l0 = __float2bfloat16(f0 - __bfloat162float(h0));
    __nv_bfloat16 l1 = __float2bfloat16(f1 - __bfloat162float(h1));
    uint32_t hp = ((uint32_t)__bfloat16_as_ushort(h1) << 16) | __bfloat16_as_ushort(h0);
    uint32_t lp = ((uint32_t)__bfloat16_as_ushort(l1) << 16) | __bfloat16_as_ushort(l0);
    int off = k * 512 + np * 4;
    int sw = off ^ ((k & 7) << 4);
    size_t tb = (size_t)chunk * 32768;
    *(uint32_t*)((char*)wh + tb + sw) = hp;
    *(uint32_t*)((char*)wl + tb + sw) = lp;
}

// ---------------- conv1: 1->256, 9x9, s1, 64->56, NHWC bf16 hi/lo out ----------------
// 28x28 output tile per CTA; thread = 4 positions x 4 oc register tile.
__global__ __launch_bounds__(196)
void conv1_kernel(const float* __restrict__ x, const float* __restrict__ w,
                  const float* __restrict__ bias,
                  __nv_bfloat16* __restrict__ oh, __nv_bfloat16* __restrict__ ol) {
    __shared__ float s_in[36 * 36];
    __shared__ float s_w[4 * 81];
    int tid = threadIdx.x;
    int tileY = blockIdx.x >> 1, tileX = blockIdx.x & 1;
    int b = blockIdx.z;
    int ocg = blockIdx.y;

    for (int idx = tid; idx < 1296; idx += 196) {
        int r = idx / 36, cc = idx % 36;
        s_in[idx] = x[((size_t)b * 64 + tileY * 28 + r) * 64 + tileX * 28 + cc];
    }
    int sy = tid / 14, sx = tid % 14;

    for (int oi = 0; oi < 32; oi += 4) {
        __syncthreads();
        for (int idx = tid; idx < 4 * 81; idx += 196) {
            int o = idx / 81, k = idx % 81;
            s_w[idx] = w[(size_t)(ocg * 32 + oi + o) * 81 + k];
        }
        __syncthreads();
        float acc[2][2][4];
        #pragma unroll
        for (int a = 0; a < 2; a++)
            #pragma unroll
            for (int q = 0; q < 2; q++)
                #pragma unroll
                for (int o = 0; o < 4; o++) acc[a][q][o] = 0.f;
        for (int ky = 0; ky < 9; ky++) {
            #pragma unroll
            for (int kx = 0; kx < 9; kx++) {
                int k = ky * 9 + kx;
                float w0 = s_w[k], w1 = s_w[81 + k], w2 = s_w[162 + k], w3 = s_w[243 + k];
                #pragma unroll
                for (int a = 0; a < 2; a++) {
                    #pragma unroll
                    for (int q = 0; q < 2; q++) {
                        float v = s_in[(sy + 14 * a + ky) * 36 + sx + 14 * q + kx];
                        acc[a][q][0] += v * w0;
                        acc[a][q][1] += v * w1;
                        acc[a][q][2] += v * w2;
                        acc[a][q][3] += v * w3;
                    }
                }
            }
        }
        int oc = ocg * 32 + oi;
        float b0 = bias[oc], b1 = bias[oc + 1], b2 = bias[oc + 2], b3 = bias[oc + 3];
        #pragma unroll
        for (int a = 0; a < 2; a++) {
            #pragma unroll
            for (int q = 0; q < 2; q++) {
                int oy = tileY * 28 + a * 14 + sy;
                int ox = tileX * 28 + q * 14 + sx;
                size_t ob = ((size_t)(b * 56 + oy) * 56 + ox) * 256 + oc;
                float v[4];
                v[0] = fmaxf(acc[a][q][0] + b0, 0.f);
                v[1] = fmaxf(acc[a][q][1] + b1, 0.f);
                v[2] = fmaxf(acc[a][q][2] + b2, 0.f);
                v[3] = fmaxf(acc[a][q][3] + b3, 0.f);
                ushort hh[4], ll[4];
                #pragma unroll
                for (int o = 0; o < 4; o++) {
                    __nv_bfloat16 h = __float2bfloat16(v[o]);
                    __nv_bfloat16 l = __float2bfloat16(v[o] - __bfloat162float(h));
                    hh[o] = __bfloat16_as_ushort(h);
                    ll[o] = __bfloat16_as_ushort(l);
                }
                *(uint2*)(oh + ob) = make_uint2(((uint32_t)hh[1] << 16) | hh[0],
                                                ((uint32_t)hh[3] << 16) | hh[2]);
                *(uint2*)(ol + ob) = make_uint2(((uint32_t)ll[1] << 16) | ll[0],
                                                ((uint32_t)ll[3] << 16) | ll[2]);
            }
        }
    }
}

// ---------------- HMMA implicit-GEMM conv, 2-stage cp.async, ONE sync per chunk ----------------
// Block: 512 thr (16 warps, 4Mx4N); tile M=128 pos x N=256 oc; warp tile 32x64.
// SMEM stage (96KB): Ah 16K | Al 16K | Bh 32K | Bl 32K. 2 stages.
#define STG_STRIDE 98304
#define SMEM_CONV_TOTAL (2 * STG_STRIDE)

template<int IH, int IW, int OH, int OW, int KW, int STRIDE, int NCHUNK, int KSPLIT, int NPOS>
__global__ __launch_bounds__(512, 1)
void conv_mma_kernel(const __nv_bfloat16* __restrict__ inh,
                     const __nv_bfloat16* __restrict__ inl,
                     const __nv_bfloat16* __restrict__ wh,
                     const __nv_bfloat16* __restrict__ wl,
                     float* __restrict__ part) {
    extern __shared__ char smem[];
    const uint32_t sb = smem_to_u32(smem);
    const int tid = threadIdx.x;
    const int wid = tid >> 5, lid = tid & 31;
    const int tile = blockIdx.x;

    // A fill identity: row r = tid>>2 (0..127), sp = tid&3 (2 x 16B segs each)
    const int r = tid >> 2, sp = tid & 3;
    const int p_mine = tile * 128 + r;
    const bool pvalid = p_mine < NPOS;
    int pb = 0, pr = 0, pcx = 0;
    if (pvalid) {
        pb = p_mine / (OH * OW);
        int rem = p_mine - pb * (OH * OW);
        pr = rem / OW;
        pcx = rem - pr * OW;
    }
    const int asz = pvalid ? 16 : 0;

    const int wm = wid >> 2, wn = wid & 3;
    const int lane15 = lid & 15, lane16 = lid >> 4;
    const int gid = lid >> 2, tig = lid & 3;

    float acc[2][8][4];
    #pragma unroll
    for (int ma = 0; ma < 2; ma++)
        #pragma unroll
        for (int na = 0; na < 8; na++)
            #pragma unroll
            for (int q = 0; q < 4; q++) acc[ma][na][q] = 0.f;

    const int NC = NCHUNK / KSPLIT;
    const int coff = blockIdx.y * NC;

    auto fill = [&](int stage, int chunk) {
        uint32_t s0 = sb + stage * STG_STRIDE;
        // B: straight copy of pre-swizzled 32KB hi + 32KB lo
        const char* bh = (const char*)(wh + (size_t)chunk * 16384);
        const char* bl = (const char*)(wl + (size_t)chunk * 16384);
        #pragma unroll
        for (int i = 0; i < 4; i++) {
            uint32_t u = (tid + i * 512) * 16;
            CP_ASYNC16(s0 + 32768 + u, bh + u, 16);
            CP_ASYNC16(s0 + 65536 + u, bl + u, 16);
        }
        // A: gather NHWC bf16 rows (64 ch = 128B hi + 128B lo)
        const int kyx = chunk >> 2;
        const int ic0 = (chunk & 3) * 64;
        const int ky = kyx / KW, kx = kyx % KW;
        size_t srcbase = 0;
        if (pvalid) {
            int iy = pr * STRIDE + ky, ix = pcx * STRIDE + kx;
            srcbase = (((size_t)pb * IH + iy) * IW + ix) * 256 + ic0;
        }
        #pragma unroll
        for (int q = 0; q < 2; q++) {
            int seg = sp * 2 + q;
            uint32_t off = r * 128 + seg * 16;
            uint32_t sw = off ^ ((r & 7) << 4);
            CP_ASYNC16(s0 + sw,         (const char*)(inh + srcbase + seg * 8), asz);
            CP_ASYNC16(s0 + 16384 + sw, (const char*)(inl + srcbase + seg * 8), asz);
        }
    };

    fill(0, coff);
    CP_COMMIT();

    for (int i = 0; i < NC; ++i) {
        CP_WAIT(0);            // fill(i) complete (fill(i+1) not yet issued)
        __syncthreads();       // also guards stage (i+1)&1 reads from compute(i-1)
        if (i + 1 < NC) {      // prefetch next chunk; lands during compute(i)
            fill((i + 1) & 1, coff + i + 1);
            CP_COMMIT();
        }

        const uint32_t s0 = sb + (i & 1) * STG_STRIDE;
        #pragma unroll
        for (int ks = 0; ks < 4; ks++) {
            uint32_t Bh[8][2], Bl[8][2];
            const int brow = ks * 16 + lane15;
            #pragma unroll
            for (int q = 0; q < 4; q++) {
                uint32_t off = brow * 512 + wn * 128 + q * 32 + lane16 * 16;
                uint32_t sw = off ^ ((brow & 7) << 4);
                ldsm_x4_t(Bh[2*q][0], Bh[2*q][1], Bh[2*q+1][0], Bh[2*q+1][1], s0 + 32768 + sw);
                ldsm_x4_t(Bl[2*q][0], Bl[2*q][1], Bl[2*q+1][0], Bl[2*q+1][1], s0 + 65536 + sw);
            }
            #pragma unroll
            for (int ma = 0; ma < 2; ma++) {
                const int arow = wm * 32 + ma * 16 + lane15;
                uint32_t offA = arow * 128 + ks * 32 + lane16 * 16;
                uint32_t swA = offA ^ ((arow & 7) << 4);
                uint32_t a[4];
                ldsm_x4(a[0], a[1], a[2], a[3], s0 + swA);
                #pragma unroll
                for (int na = 0; na < 8; na++) mma16816(acc[ma][na], a, Bh[na]);
                #pragma unroll
                for (int na = 0; na < 8; na++) mma16816(acc[ma][na], a, Bl[na]);
                ldsm_x4(a[0], a[1], a[2], a[3], s0 + 16384 + swA);
                #pragma unroll
                for (int na = 0; na < 8; na++) mma16816(acc[ma][na], a, Bh[na]);
            }
        }
    }

    // ---- epilogue: fp32 partial store ----
    float* op0 = part + (size_t)blockIdx.y * NPOS * 256;
    #pragma unroll
    for (int ma = 0; ma < 2; ma++) {
        #pragma unroll
        for (int h = 0; h < 2; h++) {
            int p = tile * 128 + wm * 32 + ma * 16 + h * 8 + gid;
            if (p >= NPOS) continue;
            float* op = op0 + (size_t)p * 256 + wn * 64 + tig * 2;
            #pragma unroll
            for (int na = 0; na < 8; na++) {
                *(float2*)(op + na * 8) = make_float2(acc[ma][na][h * 2], acc[ma][na][h * 2 + 1]);
            }
        }
    }
}

// ---------------- reduce conv2 partials (2-way) -> bias+relu -> bf16 hi/lo NHWC ----------------
__global__ void reduce2_kernel(const float* __restrict__ part, const float* __restrict__ bias,
                               __nv_bfloat16* __restrict__ oh, __nv_bfloat16* __restrict__ ol) {
    size_t gid = (size_t)blockIdx.x * 256 + threadIdx.x;   // over 43264*128 pairs
    if (gid >= (size_t)43264 * 128) return;
    int p = (int)(gid >> 7);
    int oc = ((int)gid & 127) * 2;
    const float* p0 = part + (size_t)p * 256 + oc;
    const size_t half = (size_t)43264 * 256;
    float v0 = fmaxf(p0[0] + p0[half]     + bias[oc],     0.f);
    float v1 = fmaxf(p0[1] + p0[half + 1] + bias[oc + 1], 0.f);
    __nv_bfloat16 h0 = __float2bfloat16(v0);
    __nv_bfloat16 h1 = __float2bfloat16(v1);
    __nv_bfloat16 l0 = __float2bfloat16(v0 - __bfloat162float(h0));
    __nv_bfloat16 l1 = __float2bfloat16(v1 - __bfloat162float(h1));
    size_t o = (size_t)p * 256 + oc;
    *(uint32_t*)(oh + o) = ((uint32_t)__bfloat16_as_ushort(h1) << 16) | __bfloat16_as_ushort(h0);
    *(uint32_t*)(ol + o) = ((uint32_t)__bfloat16_as_ushort(l1) << 16) | __bfloat16_as_ushort(l0);
}

// ---------------- reduce pc partials (12-way) -> bias -> fp32 NCHW ----------------
__global__ void reducep_kernel(const float* __restrict__ part, const float* __restrict__ bias,
                               float* __restrict__ out) {
    int gid = blockIdx.x * 256 + threadIdx.x;   // over 7744*64 quads
    if (gid >= 7744 * 64) return;
    int p = gid >> 6, oc = (gid & 63) * 4;
    const size_t seg = (size_t)7744 * 256;
    const float* p0 = part + (size_t)p * 256 + oc;
    float4 v = *(const float4*)p0;
    #pragma unroll
    for (int k = 1; k < 12; k++) {
        float4 t = *(const float4*)(p0 + k * seg);
        v.x += t.x; v.y += t.y; v.z += t.z; v.w += t.w;
    }
    const float4 bv = *(const float4*)(bias + oc);
    v.x += bv.x; v.y += bv.y; v.z += bv.z; v.w += bv.w;
    int b = p / 484;
    int rem = p - b * 484;
    int rr = rem / 22, cx = rem - rr * 22;
    size_t base = (((size_t)b * 256 + oc) * 22 + rr) * 22 + cx;
    out[base]             = v.x;
    out[base + 484]       = v.y;
    out[base + 2 * 484]   = v.z;
    out[base + 3 * 484]   = v.w;
}

// ---------------- squash primary caps: p -> u ----------------
__global__ void squash_u_kernel() {
    int cap = blockIdx.x * 256 + threadIdx.x;
    if (cap >= BATCH * NI) return;
    const float4* pp = (const float4*)(g_p + (size_t)cap * 8);
    float4 a = pp[0], c = pp[1];
    float s2 = a.x * a.x + a.y * a.y + a.z * a.z + a.w * a.w
             + c.x * c.x + c.y * c.y + c.z * c.z + c.w * c.w;
    float f = s2 / (1.f + s2) * rsqrtf(s2 + EPSQ);
    a.x *= f; a.y *= f; a.z *= f; a.w *= f;
    c.x *= f; c.y *= f; c.z *= f; c.w *= f;
    float4* uo = (float4*)(g_u + (size_t)cap * 8);
    uo[0] = a; uo[1] = c;
}

// ---------------- u_hat (bf16 out) ----------------
__global__ __launch_bounds__(256)
void uhat_kernel(const float* __restrict__ W) {
    int gid = blockIdx.x * 256 + threadIdx.x;
    int d = gid & 15;
    int j = (gid >> 4) % 10;
    int i = gid / 160;
    if (i >= NI) return;
    const float4* Wp = (const float4*)(W + (((size_t)j * NI + i) * 16 + d) * 8);
    float4 w0 = Wp[0], w1 = Wp[1];
    for (int b = 0; b < BATCH; b++) {
        const float4* up = (const float4*)(g_u + ((size_t)b * NI + i) * 8);
        float4 u0 = up[0], u1 = up[1];
        float acc = w0.x * u0.x + w0.y * u0.y + w0.z * u0.z + w0.w * u0.w
                  + w1.x * u1.x + w1.y * u1.y + w1.z * u1.z + w1.w * u1.w;
        g_uhatb[(((size_t)b * NI + i) * 10 + j) * 16 + d] = __float2bfloat16(acc);
    }
}

// ---------------- routing: s[b,j,d] = sum_i softmax_j(u_hat*Vcum) * u_hat ----------------
__global__ __launch_bounds__(256)
void routing_s_kernel() {
    __shared__ float Vsh[160];
    __shared__ float ssh[160];
    int tid = threadIdx.x;
    int b = blockIdx.y;
    if (tid < 160) { Vsh[tid] = g_V[b * 160 + tid]; ssh[tid] = 0.f; }
    __syncthreads();
    int d = tid & 15, il = tid >> 4;
    float accj[10];
    #pragma unroll
    for (int j = 0; j < 10; j++) accj[j] = 0.f;

    const int per = NI / 32;
    int i0 = blockIdx.x * per;
    for (int i = i0 + il; i < i0 + per; i += 16) {
        const __nv_bfloat16* uh = g_uhatb + (((size_t)b * NI + i) * 10) * 16 + d;
        float uv[10], e[10];
        float m = -1e30f;
        #pragma unroll
        for (int j = 0; j < 10; j++) {
            uv[j] = __bfloat162float(uh[j * 16]);
            float l = uv[j] * Vsh[j * 16 + d];
            e[j] = l;
            m = fmaxf(m, l);
        }
        float se = 0.f;
        #pragma unroll
        for (int j = 0; j < 10; j++) { e[j] = __expf(e[j] - m); se += e[j]; }
        float inv = 1.f / se;
        #pragma unroll
        for (int j = 0; j < 10; j++) accj[j] += e[j] * inv * uv[j];
    }
    #pragma unroll
    for (int j = 0; j < 10; j++) atomicAdd(&ssh[j * 16 + d], accj[j]);
    __syncthreads();
    if (tid < 160) atomicAdd(&g_s[b * 160 + tid], ssh[tid]);
}

// ---------------- v update / final ----------------
__global__ void v_update_kernel(int last, float* __restrict__ dout) {
    __shared__ float s2sh[10];
    __shared__ float nrm[10];
    __shared__ int amax;
    int b = blockIdx.x, tid = threadIdx.x;
    int j = tid >> 4, d = tid & 15;
    if (tid < 10) s2sh[tid] = 0.f;
    __syncthreads();
    float sv = g_s[b * 160 + tid];
    atomicAdd(&s2sh[j], sv * sv);
    __syncthreads();
    float s2 = s2sh[j];
    float v = s2 / (1.f + s2) * sv * rsqrtf(s2 + EPSQ);
    if (!last) {
        g_V[b * 160 + tid] += v;
    } else {
        if (d == 0) nrm[j] = s2 / (1.f + s2) * sqrtf(s2) * rsqrtf(s2 + EPSQ);
        __syncthreads();
        if (tid == 0) {
            int bm = 0; float mx = nrm[0];
            for (int jj = 1; jj < 10; jj++)
                if (nrm[jj] > mx) { mx = nrm[jj]; bm = jj; }
            amax = bm;
        }
        if (d == 0) dout[b * 10 + j] = nrm[j];
        __syncthreads();
        g_masked[b * 160 + tid] = (j == amax) ? v : 0.f;
    }
}

// ---------------- decoder FC ----------------
__global__ void fc_kernel(const float* __restrict__ in, const float* __restrict__ W,
                          const float* __restrict__ bias, float* __restrict__ out,
                          int IN, int OUT, int act) {
    int gid = blockIdx.x * blockDim.x + threadIdx.x;
    if (gid >= BATCH * OUT) return;
    int o = gid % OUT, b = gid / OUT;
    const float* ip = in + (size_t)b * IN;
    float acc = bias[o];
    for (int k = 0; k < IN; k++) acc += ip[k] * W[(size_t)k * OUT + o];
    if (act == 1) acc = fmaxf(acc, 0.f);
    else          acc = 1.f / (1.f + __expf(-acc));
    out[gid] = acc;
}

// ---------------- launch ----------------
extern "C" void kernel_launch(void* const* d_in, const int* in_sizes, int n_in,
                              void* d_out, int out_size) {
    const float* x   = (const float*)d_in[0];
    const float* c1w = (const float*)d_in[1];
    const float* c1b = (const float*)d_in[2];
    const float* c2w = (const float*)d_in[3];
    const float* c2b = (const float*)d_in[4];
    const float* pcw = (const float*)d_in[5];
    const float* pcb = (const float*)d_in[6];
    const float* Wc  = (const float*)d_in[7];
    const float* w1  = (const float*)d_in[8];
    const float* b1  = (const float*)d_in[9];
    const float* w2  = (const float*)d_in[10];
    const float* b2  = (const float*)d_in[11];
    const float* w3  = (const float*)d_in[12];
    const float* b3  = (const float*)d_in[13];
    float* dout = (float*)d_out;

    __nv_bfloat16 *p_c1h, *p_c1l, *p_c2h, *p_c2l, *p_w2h, *p_w2l, *p_wph, *p_wpl;
    float *p_part, *p_p, *p_s, *p_V, *p_masked, *p_d1, *p_d2;
    cudaGetSymbolAddress((void**)&p_c1h, g_c1h);
    cudaGetSymbolAddress((void**)&p_c1l, g_c1l);
    cudaGetSymbolAddress((void**)&p_c2h, g_c2h);
    cudaGetSymbolAddress((void**)&p_c2l, g_c2l);
    cudaGetSymbolAddress((void**)&p_part, g_part);
    cudaGetSymbolAddress((void**)&p_p,  g_p);
    cudaGetSymbolAddress((void**)&p_w2h, g_w2h);
    cudaGetSymbolAddress((void**)&p_w2l, g_w2l);
    cudaGetSymbolAddress((void**)&p_wph, g_wph);
    cudaGetSymbolAddress((void**)&p_wpl, g_wpl);
    cudaGetSymbolAddress((void**)&p_s,  g_s);
    cudaGetSymbolAddress((void**)&p_V,  g_V);
    cudaGetSymbolAddress((void**)&p_masked, g_masked);
    cudaGetSymbolAddress((void**)&p_d1, g_d1);
    cudaGetSymbolAddress((void**)&p_d2, g_d2);

    // conv2: IH=56 OH=52 KW=5 S=1 NCHUNK=100 KSPLIT=2 NPOS=43264
    auto conv2 = conv_mma_kernel<56, 56, 52, 52, 5, 1, 100, 2, 43264>;
    // pc: IH=52 OH=22 KW=9 S=2 NCHUNK=324 KSPLIT=12 NPOS=7744
    auto convp = conv_mma_kernel<52, 52, 22, 22, 9, 2, 324, 12, 7744>;
    cudaFuncSetAttribute(conv2, cudaFuncAttributeMaxDynamicSharedMemorySize, SMEM_CONV_TOTAL);
    cudaFuncSetAttribute(convp, cudaFuncAttributeMaxDynamicSharedMemorySize, SMEM_CONV_TOTAL);

    // weight split/swizzle transforms
    transform_wsplit_kernel<<<(100 * 64 * 128 + 255) / 256, 256>>>(c2w, p_w2h, p_w2l, 5, 5, 100);
    transform_wsplit_kernel<<<(324 * 64 * 128 + 255) / 256, 256>>>(pcw, p_wph, p_wpl, 9, 9, 324);

    // conv1 (NHWC bf16 hi/lo out)
    conv1_kernel<<<dim3(4, 8, 16), 196>>>(x, c1w, c1b, p_c1h, p_c1l);

    // conv2: split-K=2 partials, then reduce (bias+relu -> bf16 hi/lo)
    conv2<<<dim3(338, 2), 512, SMEM_CONV_TOTAL>>>(p_c1h, p_c1l, p_w2h, p_w2l, p_part);
    reduce2_kernel<<<(int)(((size_t)43264 * 128 + 255) / 256), 256>>>(p_part, c2b, p_c2h, p_c2l);

    // pc: split-K=12 partials, then reduce (bias -> fp32 NCHW)
    convp<<<dim3(61, 12), 512, SMEM_CONV_TOTAL>>>(p_c2h, p_c2l, p_wph, p_wpl, p_part);
    reducep_kernel<<<(7744 * 64 + 255) / 256, 256>>>(p_part, pcb, p_p);

    squash_u_kernel<<<(BATCH * NI + 255) / 256, 256>>>();
    uhat_kernel<<<((size_t)NI * 160 + 255) / 256, 256>>>(Wc);

    cudaMemsetAsync(p_V, 0, BATCH * 160 * sizeof(float));
    for (int r = 0; r < 3; r++) {
        cudaMemsetAsync(p_s, 0, BATCH * 160 * sizeof(float));
        routing_s_kernel<<<dim3(32, 16), 256>>>();
        v_update_kernel<<<16, 160>>>(r == 2 ? 1 : 0, dout);
    }

    fc_kernel<<<(BATCH * 512 + 255) / 256, 256>>>(p_masked, w1, b1, p_d1, 160, 512, 1);
    fc_kernel<<<(BATCH * 1024 + 255) / 256, 256>>>(p_d1, w2, b2, p_d2, 512, 1024, 1);
    fc_kernel<<<(BATCH * 4096 + 255) / 256, 256>>>(p_d2, w3, b3, dout + 160, 1024, 4096, 2);
}